// round 13
// baseline (speedup 1.0000x reference)
#include <cuda_runtime.h>
#include <cuda_fp16.h>
#include <math.h>
#include <stdint.h>

constexpr int B_   = 256;
constexpr int Q_   = 512;
constexpr int D_   = 32;
constexpr int H_   = 192;
constexpr int HID_ = 384;
constexpr int INC_ = 96;     // 3*D
constexpr int BQ_  = B_ * Q_;
constexpr float PI_ = 3.14159265358979323846f;
constexpr float SPLIT_SCALE = 2048.0f;        // 2^11
constexpr float SPLIT_INV   = 1.0f / 2048.0f;

typedef unsigned long long ull;

// ------------------------- scratch (device globals) ------------------------
__device__ float g_h   [(size_t)BQ_ * H_];
__device__ float g_part[4 * B_ * HID_];
__device__ float g_rp  [BQ_ * 2];
__device__ float g_gain[(size_t)BQ_ * D_];
__device__ float g_hr  [B_ * H_];
__device__ float g_curr[B_ * D_];
// conv output + pw1 output as fp16 hi / scaled-lo split
__device__ __half g_yh [(size_t)BQ_ * H_];
__device__ __half g_yl [(size_t)BQ_ * H_];
__device__ __half g_y1h[(size_t)BQ_ * HID_];
__device__ __half g_y1l[(size_t)BQ_ * HID_];
// pre-split pw1 weights (fp16 hi / scaled-lo), [blk][n][k]
__device__ __half g_w1h[2 * HID_ * H_];
__device__ __half g_w1l[2 * HID_ * H_];
// pw2 effective bias: pw2_b[n] + sum_k grnb[k]*W2[n,k]
__device__ float g_bias2[2 * H_];
// rollout weights, float4-packed
__device__ float g_pA4 [56 * 768 * 4];
__device__ float g_bA  [768];
__device__ float g_wih4[48 * 576 * 4];

__device__ __forceinline__ float sigf(float x) { return 1.0f / (1.0f + expf(-x)); }

__device__ __forceinline__ float warp_sum(float v) {
#pragma unroll
    for (int o = 16; o > 0; o >>= 1) v += __shfl_xor_sync(0xffffffffu, v, o);
    return v;
}

// packed f32x2 helpers
__device__ __forceinline__ ull ff2(ull a, ull b, ull c) {
    ull d;
    asm("fma.rn.f32x2 %0, %1, %2, %3;" : "=l"(d) : "l"(a), "l"(b), "l"(c));
    return d;
}
__device__ __forceinline__ ull dup2(float x) {
    ull d;
    unsigned xb = __float_as_uint(x);
    asm("mov.b64 %0, {%1, %1};" : "=l"(d) : "r"(xb));
    return d;
}
__device__ __forceinline__ float lo2(ull v) { return __uint_as_float((unsigned)v); }
__device__ __forceinline__ float hi2(ull v) { return __uint_as_float((unsigned)(v >> 32)); }

// ------------------------- mma.sync helpers ---------------------------------
__device__ __forceinline__ uint32_t smem_u32(const void* p) {
    uint32_t a;
    asm("{ .reg .u64 t; cvta.to.shared.u64 t, %1; cvt.u32.u64 %0, t; }" : "=r"(a) : "l"(p));
    return a;
}
__device__ __forceinline__ void ldm_x4(uint32_t& r0, uint32_t& r1, uint32_t& r2, uint32_t& r3,
                                       uint32_t addr) {
    asm volatile("ldmatrix.sync.aligned.m8n8.x4.shared.b16 {%0,%1,%2,%3}, [%4];"
                 : "=r"(r0), "=r"(r1), "=r"(r2), "=r"(r3) : "r"(addr));
}
__device__ __forceinline__ void mma_f16(float* d, const uint32_t* a,
                                        uint32_t b0, uint32_t b1) {
    asm volatile(
        "mma.sync.aligned.m16n8k16.row.col.f32.f16.f16.f32 "
        "{%0,%1,%2,%3}, {%4,%5,%6,%7}, {%8,%9}, {%0,%1,%2,%3};"
        : "+f"(d[0]), "+f"(d[1]), "+f"(d[2]), "+f"(d[3])
        : "r"(a[0]), "r"(a[1]), "r"(a[2]), "r"(a[3]), "r"(b0), "r"(b1));
}
__device__ __forceinline__ uint32_t swz(int row, int byte) {
    return (uint32_t)(row * 128 + (byte ^ ((row & 7) << 4)));
}
__device__ __forceinline__ float geluf(float v) {
    return 0.5f * v * (1.0f + erff(v * 0.70710678118654752f));
}
// scaled split: hi = fp16(v), lo = fp16((v - hi) * 2^11)
__device__ __forceinline__ void split16(float v, __half& hi, __half& lo) {
    hi = __float2half(v);
    lo = __float2half((v - __half2float(hi)) * SPLIT_SCALE);
}

// ------------------------- tensor-core fp16 full-split GEMM -----------------
// acch += Ah*Wh ; accl += Ah*Wl' + Al'*Wh ; acc2 += Al'*Wl'
// result = acch + (accl + acc2/2^11)/2^11   (exact to fp32 accumulation)
// MODE 1: A = g_yh/l, W = g_w1h/l; out = GELU(..)+bias -> g_y1h/l + GRN partials
// MODE 2: A = g_y1h/l; W = W2 * GRN-scale (split on the fly);
//         out = .. + g_bias2 + residual -> g_h.
// Both: BN=64, CTA 128x64, 8 warps 4x2, warp tile 32x32.
template <int MODE>
__global__ __launch_bounds__(256) void k_mma(
    int blk, const float* __restrict__ bias, int K, int N,
    const float* __restrict__ W2, const float* __restrict__ grn_g)
{
    extern __shared__ char smem[];
    constexpr int BN = 64;
    constexpr int NT = 4;
    constexpr int SM_AH = 0;
    constexpr int SM_AL = SM_AH + 16384;
    constexpr int SM_WH = SM_AL + 16384;
    constexpr int SM_WL = SM_WH + BN * 128;
    constexpr int SM_AUX = SM_WL + BN * 128;
    __shared__ float sred[256];

    const uint32_t sb = smem_u32(smem);
    const int tid = threadIdx.x;
    const int wid = tid >> 5, lane = tid & 31;
    const int g = lane >> 2, t = lane & 3;
    const int quad = lane >> 3, lr = lane & 7;
    const int wrow = wid & 3;
    const int wcol = wid >> 2;
    const int m0 = blockIdx.y * 128;
    const int n0 = blockIdx.x * BN;
    const int b  = m0 >> 9;

    float* saux = reinterpret_cast<float*>(smem + SM_AUX);

    const __half* Ah = (MODE == 1) ? g_yh : g_y1h;
    const __half* Al = (MODE == 1) ? g_yl : g_y1l;
    const __half* Wh = g_w1h + (size_t)blk * HID_ * H_;
    const __half* Wl = g_w1l + (size_t)blk * HID_ * H_;

    if (MODE == 2) {
        // fused GRN scale into saux[0..HID)
        float gsum = 0.0f;
        for (int c = tid; c < HID_; c += 256) {
            float gg = sqrtf(g_part[(0 * B_ + b) * HID_ + c] +
                             g_part[(1 * B_ + b) * HID_ + c] +
                             g_part[(2 * B_ + b) * HID_ + c] +
                             g_part[(3 * B_ + b) * HID_ + c]);
            saux[c] = gg;
            gsum += gg;
        }
        sred[tid] = gsum;
        __syncthreads();
        for (int s = 128; s > 0; s >>= 1) {
            if (tid < s) sred[tid] += sred[tid + s];
            __syncthreads();
        }
        float mean = sred[0] * (1.0f / HID_);
        __syncthreads();
        for (int c = tid; c < HID_; c += 256) {
            float nx = saux[c] / (mean + 1e-6f);
            saux[c] = 1.0f + grn_g[c] * nx;
        }
        __syncthreads();
    }

    float acch[2][NT][4], accl[2][NT][4], acc2[2][NT][4];
#pragma unroll
    for (int mt = 0; mt < 2; mt++)
#pragma unroll
        for (int nt = 0; nt < NT; nt++)
#pragma unroll
            for (int j = 0; j < 4; j++) {
                acch[mt][nt][j] = 0.0f; accl[mt][nt][j] = 0.0f; acc2[mt][nt][j] = 0.0f;
            }

    const int nchunks = K >> 6;
    for (int kc = 0; kc < nchunks; kc++) {
        // ---- stage A chunk: vectorized copy of pre-split halves ----
#pragma unroll
        for (int it = 0; it < 4; it++) {
            int id = tid + it * 256;            // 1024 16B-chunks
            int r = id >> 3, k8 = (id & 7) * 8;
            uint32_t off = swz(r, k8 * 2);
            size_t src = (size_t)(m0 + r) * K + kc * 64 + k8;
            *reinterpret_cast<uint4*>(smem + SM_AH + off) =
                *reinterpret_cast<const uint4*>(Ah + src);
            *reinterpret_cast<uint4*>(smem + SM_AL + off) =
                *reinterpret_cast<const uint4*>(Al + src);
        }
        // ---- stage W chunk ----
        if (MODE == 1) {
#pragma unroll
            for (int it = 0; it < 2; it++) {
                int id = tid + it * 256;        // 512 16B-chunks
                int r = id >> 3, k8 = (id & 7) * 8;
                uint32_t off = swz(r, k8 * 2);
                size_t src = (size_t)(n0 + r) * K + kc * 64 + k8;
                *reinterpret_cast<uint4*>(smem + SM_WH + off) =
                    *reinterpret_cast<const uint4*>(Wh + src);
                *reinterpret_cast<uint4*>(smem + SM_WL + off) =
                    *reinterpret_cast<const uint4*>(Wl + src);
            }
        } else {
            // scale W2 by GRN scale along k, split on the fly
#pragma unroll
            for (int it = 0; it < 4; it++) {
                int id = tid + it * 256;        // 1024 float4 groups
                int r = id >> 4, c4 = (id & 15) * 4;
                int gk = kc * 64 + c4;
                float4 w = *reinterpret_cast<const float4*>(
                    W2 + (size_t)(n0 + r) * K + gk);
                w.x *= saux[gk + 0]; w.y *= saux[gk + 1];
                w.z *= saux[gk + 2]; w.w *= saux[gk + 3];
                __half h0, l0, h1, l1, h2, l2, h3, l3;
                split16(w.x, h0, l0); split16(w.y, h1, l1);
                split16(w.z, h2, l2); split16(w.w, h3, l3);
                uint32_t off = swz(r, c4 * 2);
                __half2* ph = reinterpret_cast<__half2*>(smem + SM_WH + off);
                ph[0] = __halves2half2(h0, h1);
                ph[1] = __halves2half2(h2, h3);
                __half2* pl = reinterpret_cast<__half2*>(smem + SM_WL + off);
                pl[0] = __halves2half2(l0, l1);
                pl[1] = __halves2half2(l2, l3);
            }
        }
        __syncthreads();

        // ---- 4 k-steps of 16 ----
#pragma unroll
        for (int ks = 0; ks < 4; ks++) {
            uint32_t ah[2][4], al[2][4];
#pragma unroll
            for (int mt = 0; mt < 2; mt++) {
                int arow = wrow * 32 + mt * 16 + (quad & 1) * 8 + lr;
                int abyte = ks * 32 + (quad >> 1) * 16;
                uint32_t aoff = swz(arow, abyte);
                ldm_x4(ah[mt][0], ah[mt][1], ah[mt][2], ah[mt][3], sb + SM_AH + aoff);
                ldm_x4(al[mt][0], al[mt][1], al[mt][2], al[mt][3], sb + SM_AL + aoff);
            }
#pragma unroll
            for (int np = 0; np < 2; np++) {
                int brow = wcol * 32 + np * 16 + (quad >> 1) * 8 + lr;
                int bbyte = ks * 32 + (quad & 1) * 16;
                uint32_t boff = swz(brow, bbyte);
                uint32_t bh[4], bl[4];
                ldm_x4(bh[0], bh[1], bh[2], bh[3], sb + SM_WH + boff);
                ldm_x4(bl[0], bl[1], bl[2], bl[3], sb + SM_WL + boff);
#pragma unroll
                for (int mt = 0; mt < 2; mt++) {
                    mma_f16(acch[mt][np * 2 + 0], ah[mt], bh[0], bh[1]);
                    mma_f16(accl[mt][np * 2 + 0], ah[mt], bl[0], bl[1]);
                    mma_f16(accl[mt][np * 2 + 0], al[mt], bh[0], bh[1]);
                    mma_f16(acc2[mt][np * 2 + 0], al[mt], bl[0], bl[1]);
                    mma_f16(acch[mt][np * 2 + 1], ah[mt], bh[2], bh[3]);
                    mma_f16(accl[mt][np * 2 + 1], ah[mt], bl[2], bl[3]);
                    mma_f16(accl[mt][np * 2 + 1], al[mt], bh[2], bh[3]);
                    mma_f16(acc2[mt][np * 2 + 1], al[mt], bl[2], bl[3]);
                }
            }
        }
        __syncthreads();
    }

    // ---- epilogue ----
    float s2[NT][2];
    if (MODE == 1) {
#pragma unroll
        for (int nt = 0; nt < NT; nt++) { s2[nt][0] = 0.0f; s2[nt][1] = 0.0f; }
    }

#pragma unroll
    for (int mt = 0; mt < 2; mt++) {
#pragma unroll
        for (int h = 0; h < 2; h++) {
            int row = m0 + wrow * 32 + mt * 16 + h * 8 + g;
#pragma unroll
            for (int nt = 0; nt < NT; nt++) {
                int col = n0 + wcol * 32 + nt * 8 + 2 * t;
                float bb0, bb1;
                if (MODE == 1) { bb0 = bias[col]; bb1 = bias[col + 1]; }
                else { bb0 = g_bias2[blk * H_ + col]; bb1 = g_bias2[blk * H_ + col + 1]; }
                float c0 = fmaf(acc2[mt][nt][h * 2 + 0], SPLIT_INV, accl[mt][nt][h * 2 + 0]);
                float c1 = fmaf(acc2[mt][nt][h * 2 + 1], SPLIT_INV, accl[mt][nt][h * 2 + 1]);
                float f0 = fmaf(c0, SPLIT_INV, acch[mt][nt][h * 2 + 0]) + bb0;
                float f1 = fmaf(c1, SPLIT_INV, acch[mt][nt][h * 2 + 1]) + bb1;
                if (MODE == 1) {
                    f0 = geluf(f0); f1 = geluf(f1);
                    s2[nt][0] = fmaf(f0, f0, s2[nt][0]);
                    s2[nt][1] = fmaf(f1, f1, s2[nt][1]);
                    __half h0, l0, h1, l1;
                    split16(f0, h0, l0); split16(f1, h1, l1);
                    *reinterpret_cast<__half2*>(g_y1h + (size_t)row * N + col) =
                        __halves2half2(h0, h1);
                    *reinterpret_cast<__half2*>(g_y1l + (size_t)row * N + col) =
                        __halves2half2(l0, l1);
                } else {
                    float2 r = *reinterpret_cast<const float2*>(g_h + (size_t)row * N + col);
                    f0 += r.x; f1 += r.y;
                    float2 o = make_float2(f0, f1);
                    *reinterpret_cast<float2*>(g_h + (size_t)row * N + col) = o;
                }
            }
        }
    }

    if (MODE == 1) {
#pragma unroll
        for (int nt = 0; nt < NT; nt++) {
#pragma unroll
            for (int j = 0; j < 2; j++) {
                float v = s2[nt][j];
                v += __shfl_xor_sync(0xffffffffu, v, 4);
                v += __shfl_xor_sync(0xffffffffu, v, 8);
                v += __shfl_xor_sync(0xffffffffu, v, 16);
                if (g == 0)
                    saux[wrow * 64 + wcol * 32 + nt * 8 + 2 * t + j] = v;
            }
        }
        __syncthreads();
        if (tid < 64) {
            float s = saux[tid] + saux[64 + tid] + saux[128 + tid] + saux[192 + tid];
            int quarter = (m0 >> 7) & 3;
            g_part[(quarter * B_ + b) * HID_ + n0 + tid] = s;
        }
    }
}

// ------------------------- scalar SGEMM for input projection ----------------
__global__ __launch_bounds__(256) void k_gemm3(
    const float* __restrict__ W, const float* __restrict__ bias,
    int K, int N, const float* __restrict__ x_in)
{
    constexpr int BM = 128, BN = 64, BK = 16, TN = 4;
    constexpr int AS = 132, BS = BN + 4;
    __shared__ float As[BK * AS];
    __shared__ float Bs[BK * BS];

    const int m0 = blockIdx.y * BM;
    const int n0 = blockIdx.x * BN;
    const int tid = threadIdx.x;
    const int tx = tid & 15;
    const int ty = tid >> 4;

    ull acc[4][TN];
#pragma unroll
    for (int p = 0; p < 4; p++)
#pragma unroll
        for (int j = 0; j < TN; j++) acc[p][j] = 0ull;

    for (int k0 = 0; k0 < K; k0 += BK) {
#pragma unroll
        for (int it = 0; it < 2; it++) {
            int f = tid + it * 256;
            int row = f >> 2;
            int k4  = f & 3;
            int grow = m0 + row;
            int gk = k0 + k4 * 4;
            int t = grow & (Q_ - 1);
            int g = gk >> 5;
            int d = gk & 31;
            const float* xr = x_in + (size_t)grow * D_ + d;
            float4 x0 = *reinterpret_cast<const float4*>(xr);
            float4 v;
            if (g == 0) {
                v = x0;
            } else {
                float4 x1 = (t >= 1) ? *reinterpret_cast<const float4*>(xr - D_) : x0;
                if (g == 1) {
                    v = make_float4(x0.x - x1.x, x0.y - x1.y, x0.z - x1.z, x0.w - x1.w);
                } else {
                    float4 x2 = (t >= 2) ? *reinterpret_cast<const float4*>(xr - 2 * D_) : x1;
                    v = make_float4(x0.x - 2.0f * x1.x + x2.x,
                                    x0.y - 2.0f * x1.y + x2.y,
                                    x0.z - 2.0f * x1.z + x2.z,
                                    x0.w - 2.0f * x1.w + x2.w);
                }
            }
            As[(k4 * 4 + 0) * AS + row] = v.x;
            As[(k4 * 4 + 1) * AS + row] = v.y;
            As[(k4 * 4 + 2) * AS + row] = v.z;
            As[(k4 * 4 + 3) * AS + row] = v.w;
        }
        {
            int row = tid >> 2;
            int k4  = tid & 3;
            float4 v = *reinterpret_cast<const float4*>(W + (size_t)(n0 + row) * K + (k0 + k4 * 4));
            Bs[(k4 * 4 + 0) * BS + row] = v.x;
            Bs[(k4 * 4 + 1) * BS + row] = v.y;
            Bs[(k4 * 4 + 2) * BS + row] = v.z;
            Bs[(k4 * 4 + 3) * BS + row] = v.w;
        }
        __syncthreads();

#pragma unroll
        for (int kk = 0; kk < BK; kk++) {
            const ulonglong2* a2 = reinterpret_cast<const ulonglong2*>(&As[kk * AS + ty * 8]);
            ulonglong2 q0 = a2[0], q1 = a2[1];
            ull ap[4];
            ap[0] = q0.x; ap[1] = q0.y; ap[2] = q1.x; ap[3] = q1.y;
            float4 tb = *reinterpret_cast<const float4*>(&Bs[kk * BS + tx * TN]);
            ull bd[4];
            bd[0] = dup2(tb.x); bd[1] = dup2(tb.y); bd[2] = dup2(tb.z); bd[3] = dup2(tb.w);
#pragma unroll
            for (int p = 0; p < 4; p++)
#pragma unroll
                for (int j = 0; j < TN; j++)
                    acc[p][j] = ff2(ap[p], bd[j], acc[p][j]);
        }
        __syncthreads();
    }

    float4 bia = *reinterpret_cast<const float4*>(bias + n0 + tx * TN);
#pragma unroll
    for (int p = 0; p < 4; p++) {
#pragma unroll
        for (int hf = 0; hf < 2; hf++) {
            int row = m0 + ty * 8 + p * 2 + hf;
            float4 o;
            o.x = (hf ? hi2(acc[p][0]) : lo2(acc[p][0])) + bia.x;
            o.y = (hf ? hi2(acc[p][1]) : lo2(acc[p][1])) + bia.y;
            o.z = (hf ? hi2(acc[p][2]) : lo2(acc[p][2])) + bia.z;
            o.w = (hf ? hi2(acc[p][3]) : lo2(acc[p][3])) + bia.w;
            *reinterpret_cast<float4*>(g_h + (size_t)row * N + n0 + tx * TN) = o;
        }
    }
}

// ------------------------- depthwise conv + LN -> fp16 split ----------------
__global__ __launch_bounds__(256) void k_conv(
    const float* __restrict__ dw_w, const float* __restrict__ dw_b,
    const float* __restrict__ ln_w, const float* __restrict__ ln_b)
{
    __shared__ float s_in[24][H_];
    __shared__ float s_out[16][H_];
    __shared__ float s_w[H_ * 9];
    __shared__ float s_b[H_];

    const int b  = blockIdx.y;
    const int t0 = blockIdx.x * 16;
    const int tid = threadIdx.x;

    for (int i = tid; i < H_ * 9; i += 256) s_w[i] = dw_w[i];
    for (int i = tid; i < H_; i += 256) s_b[i] = dw_b[i];
    for (int i = tid; i < 24 * H_; i += 256) {
        int r = i / H_, ch = i % H_;
        int t = t0 + r - 4;
        t = min(max(t, 0), Q_ - 1);
        s_in[r][ch] = g_h[((size_t)b * Q_ + t) * H_ + ch];
    }
    __syncthreads();

    for (int i = tid; i < 16 * H_; i += 256) {
        int r = i / H_, ch = i % H_;
        float acc = s_b[ch];
#pragma unroll
        for (int k = 0; k < 9; k++) acc = fmaf(s_in[r + k][ch], s_w[ch * 9 + k], acc);
        s_out[r][ch] = acc;
    }
    __syncthreads();

    const int wid = tid >> 5, lane = tid & 31;
#pragma unroll
    for (int rr = 0; rr < 2; rr++) {
        int r = wid * 2 + rr;
        float v[6], sum = 0.0f;
#pragma unroll
        for (int j = 0; j < 6; j++) { v[j] = s_out[r][j * 32 + lane]; sum += v[j]; }
        sum = warp_sum(sum);
        float mean = sum * (1.0f / H_);
        float var = 0.0f;
#pragma unroll
        for (int j = 0; j < 6; j++) { float d = v[j] - mean; var = fmaf(d, d, var); }
        var = warp_sum(var) * (1.0f / H_);
        float inv = rsqrtf(var + 1e-5f);
        size_t base = ((size_t)b * Q_ + t0 + r) * H_;
#pragma unroll
        for (int j = 0; j < 6; j++) {
            int ch = j * 32 + lane;
            float val = (v[j] - mean) * inv * ln_w[ch] + ln_b[ch];
            __half hi, lo;
            split16(val, hi, lo);
            g_yh[base + ch] = hi;
            g_yl[base + ch] = lo;
        }
    }
}

// ------------------------- out-LN + rho/phi/gain -----------------------------
__global__ __launch_bounds__(256) void k_rpg(
    const float* __restrict__ out_ln_w, const float* __restrict__ out_ln_b,
    const float* __restrict__ fc_rp_w, const float* __restrict__ fc_rp_b,
    const float* __restrict__ fc_gain_w, const float* __restrict__ fc_gain_b)
{
    const int wid = threadIdx.x >> 5, lane = threadIdx.x & 31;
    const int row = blockIdx.x * 8 + wid;
    const float* hp = g_h + (size_t)row * H_;

    float v[6], sum = 0.0f;
#pragma unroll
    for (int j = 0; j < 6; j++) { v[j] = hp[j * 32 + lane]; sum += v[j]; }
    sum = warp_sum(sum);
    float mean = sum * (1.0f / H_);
    float var = 0.0f;
#pragma unroll
    for (int j = 0; j < 6; j++) { float d = v[j] - mean; var = fmaf(d, d, var); }
    var = warp_sum(var) * (1.0f / H_);
    float inv = rsqrtf(var + 1e-5f);

    float hn[6];
#pragma unroll
    for (int j = 0; j < 6; j++) {
        int ch = j * 32 + lane;
        hn[j] = (v[j] - mean) * inv * out_ln_w[ch] + out_ln_b[ch];
    }

    int t = row & (Q_ - 1), b = row >> 9;
    if (t == Q_ - 1) {
#pragma unroll
        for (int j = 0; j < 6; j++) g_hr[b * H_ + j * 32 + lane] = hn[j];
    }

#pragma unroll
    for (int o = 0; o < 2; o++) {
        float a = 0.0f;
#pragma unroll
        for (int j = 0; j < 6; j++) a = fmaf(hn[j], fc_rp_w[o * H_ + j * 32 + lane], a);
        a = warp_sum(a);
        if (lane == 0) {
            float z = a + fc_rp_b[o];
            g_rp[row * 2 + o] = (o == 0) ? 1.25f * sigf(z) : PI_ * tanhf(z);
        }
    }
    for (int d = 0; d < D_; d++) {
        float a = 0.0f;
#pragma unroll
        for (int j = 0; j < 6; j++) a = fmaf(hn[j], fc_gain_w[d * H_ + j * 32 + lane], a);
        a = warp_sum(a);
        if (lane == 0) g_gain[(size_t)row * D_ + d] = sigf(a + fc_gain_b[d]);
    }
}

// ------------------------- Kalman scan ---------------------------------------
__global__ void k_scan(const float* __restrict__ x_in) {
    const int wid = threadIdx.x >> 5, lane = threadIdx.x & 31;
    const int b = blockIdx.x * 4 + wid;
    const int base = b * Q_;

    float x  = x_in[(size_t)base * D_ + lane];
    float2 rp = *reinterpret_cast<const float2*>(g_rp + base * 2);
    float gn = g_gain[(size_t)base * D_ + lane];
    float y  = x;

    for (int t = 0; t < Q_; t++) {
        float2 rp_n = rp; float gn_n = gn, y_n = y;
        if (t + 1 < Q_) {
            rp_n = *reinterpret_cast<const float2*>(g_rp + (base + t + 1) * 2);
            gn_n = g_gain[(size_t)(base + t + 1) * D_ + lane];
            y_n  = x_in[(size_t)(base + t + 1) * D_ + lane];
        }
        float s, c;
        sincosf(rp.y, &s, &c);
        float partner = __shfl_xor_sync(0xffffffffu, x, 16);
        float xp = (lane < 16) ? rp.x * (c * x - s * partner)
                               : rp.x * (s * partner + c * x);
        x = xp + gn * (y - xp);
        rp = rp_n; gn = gn_n; y = y_n;
    }
    g_curr[b * D_ + lane] = x;
}

// ------------------------- packing ------------------------------------------
__global__ void k_pack(const float* __restrict__ roll_in_w, const float* __restrict__ roll_in_b,
                       const float* __restrict__ gru_whh, const float* __restrict__ gru_bhh,
                       const float* __restrict__ gru_wih,
                       const float* __restrict__ b_pw1_w, const float* __restrict__ b_pw2_w,
                       const float* __restrict__ b_pw2_b, const float* __restrict__ b_grn_b)
{
    int i = blockIdx.x * 256 + threadIdx.x;
    constexpr int NA = 56 * 768 * 4;
    constexpr int NB = NA + 768;
    constexpr int NW = NB + 48 * 576 * 4;
    constexpr int NW1 = NW + 2 * HID_ * H_;
    constexpr int NB2 = NW1 + 2 * H_;
    if (i < NA) {
        int k4 = i / (768 * 4);
        int rem = i % (768 * 4);
        int c = rem >> 2;
        int j = rem & 3;
        int k = 4 * k4 + j;
        float v;
        if (c < 192)      v = roll_in_w[c * 224 + k];
        else if (k < 192) v = gru_whh[(c - 192) * 192 + k];
        else              v = 0.0f;
        g_pA4[i] = v;
    } else if (i < NB) {
        int c = i - NA;
        g_bA[c] = (c < 192) ? roll_in_b[c] : gru_bhh[c - 192];
    } else if (i < NW) {
        int t = i - NB;
        int k4 = t / (576 * 4);
        int rem = t % (576 * 4);
        int o = rem >> 2;
        int j = rem & 3;
        g_wih4[t] = gru_wih[o * 192 + 4 * k4 + j];
    } else if (i < NW1) {
        int j = i - NW;
        __half hi, lo;
        split16(b_pw1_w[j], hi, lo);
        g_w1h[j] = hi;
        g_w1l[j] = lo;
    } else if (i < NB2) {
        int j = i - NW1;             // [blk*H_ + n]
        int blk = j / H_, n = j % H_;
        const float* w = b_pw2_w + (size_t)blk * H_ * HID_ + (size_t)n * HID_;
        const float* gb = b_grn_b + blk * HID_;
        float s = b_pw2_b[blk * H_ + n];
        for (int k = 0; k < HID_; k++) s = fmaf(gb[k], w[k], s);
        g_bias2[j] = s;
    }
}

// ------------------------- persistent GRU rollout ----------------------------
__global__ __launch_bounds__(256) void k_roll(
    const float* __restrict__ gru_bih,
    const float* __restrict__ roll_ln_w, const float* __restrict__ roll_ln_b,
    const float* __restrict__ fc_rp_r_w, const float* __restrict__ fc_rp_r_b,
    float* __restrict__ out, int w_out)
{
    __shared__ float sSt[224][4];
    __shared__ float sx [192][4];
    __shared__ float sgh[4][576];
    __shared__ float sgi[4][576];
    __shared__ float spre[4][192];

    const int r0 = blockIdx.x * 4;
    const int tid = threadIdx.x;
    const int wid = tid >> 5, lane = tid & 31;

    const float4* pA4  = reinterpret_cast<const float4*>(g_pA4);
    const float4* wih4 = reinterpret_cast<const float4*>(g_wih4);

    for (int i = tid; i < 4 * 224; i += 256) {
        int r = i / 224, k = i % 224;
        sSt[k][r] = (k < 192) ? g_hr[(r0 + r) * H_ + k]
                              : g_curr[(r0 + r) * D_ + (k - 192)];
    }
    __syncthreads();

    for (int step = 0; step < w_out; step++) {
        {
            ull a01[3], a23[3];
#pragma unroll
            for (int j = 0; j < 3; j++) { a01[j] = 0ull; a23[j] = 0ull; }
#pragma unroll 4
            for (int k4 = 0; k4 < 56; k4++) {
                float4 w0 = __ldg(pA4 + k4 * 768 + tid);
                float4 w1 = __ldg(pA4 + k4 * 768 + tid + 256);
                float4 w2 = __ldg(pA4 + k4 * 768 + tid + 512);
                ull p01[4], p23[4];
#pragma unroll
                for (int j = 0; j < 4; j++) {
                    p01[j] = *reinterpret_cast<const ull*>(&sSt[k4 * 4 + j][0]);
                    p23[j] = *reinterpret_cast<const ull*>(&sSt[k4 * 4 + j][2]);
                }
                ull b;
                b = dup2(w0.x); a01[0]=ff2(p01[0],b,a01[0]); a23[0]=ff2(p23[0],b,a23[0]);
                b = dup2(w0.y); a01[0]=ff2(p01[1],b,a01[0]); a23[0]=ff2(p23[1],b,a23[0]);
                b = dup2(w0.z); a01[0]=ff2(p01[2],b,a01[0]); a23[0]=ff2(p23[2],b,a23[0]);
                b = dup2(w0.w); a01[0]=ff2(p01[3],b,a01[0]); a23[0]=ff2(p23[3],b,a23[0]);
                b = dup2(w1.x); a01[1]=ff2(p01[0],b,a01[1]); a23[1]=ff2(p23[0],b,a23[1]);
                b = dup2(w1.y); a01[1]=ff2(p01[1],b,a01[1]); a23[1]=ff2(p23[1],b,a23[1]);
                b = dup2(w1.z); a01[1]=ff2(p01[2],b,a01[1]); a23[1]=ff2(p23[2],b,a23[1]);
                b = dup2(w1.w); a01[1]=ff2(p01[3],b,a01[1]); a23[1]=ff2(p23[3],b,a23[1]);
                b = dup2(w2.x); a01[2]=ff2(p01[0],b,a01[2]); a23[2]=ff2(p23[0],b,a23[2]);
                b = dup2(w2.y); a01[2]=ff2(p01[1],b,a01[2]); a23[2]=ff2(p23[1],b,a23[2]);
                b = dup2(w2.z); a01[2]=ff2(p01[2],b,a01[2]); a23[2]=ff2(p23[2],b,a23[2]);
                b = dup2(w2.w); a01[2]=ff2(p01[3],b,a01[2]); a23[2]=ff2(p23[3],b,a23[2]);
            }
#pragma unroll
            for (int j = 0; j < 3; j++) {
                int c = tid + j * 256;
                float bia = g_bA[c];
                float v0 = lo2(a01[j]) + bia;
                float v1 = hi2(a01[j]) + bia;
                float v2 = lo2(a23[j]) + bia;
                float v3 = hi2(a23[j]) + bia;
                if (c < 192) {
                    sx[c][0] = tanhf(v0); sx[c][1] = tanhf(v1);
                    sx[c][2] = tanhf(v2); sx[c][3] = tanhf(v3);
                } else {
                    int o = c - 192;
                    sgh[0][o] = v0; sgh[1][o] = v1; sgh[2][o] = v2; sgh[3][o] = v3;
                }
            }
        }
        __syncthreads();

        {
            ull a01[3], a23[3];
#pragma unroll
            for (int j = 0; j < 3; j++) { a01[j] = 0ull; a23[j] = 0ull; }
            int o2c = (tid < 64) ? (tid + 512) : 575;
#pragma unroll 4
            for (int k4 = 0; k4 < 48; k4++) {
                float4 w0 = __ldg(wih4 + k4 * 576 + tid);
                float4 w1 = __ldg(wih4 + k4 * 576 + tid + 256);
                float4 w2 = __ldg(wih4 + k4 * 576 + o2c);
                ull p01[4], p23[4];
#pragma unroll
                for (int j = 0; j < 4; j++) {
                    p01[j] = *reinterpret_cast<const ull*>(&sx[k4 * 4 + j][0]);
                    p23[j] = *reinterpret_cast<const ull*>(&sx[k4 * 4 + j][2]);
                }
                ull b;
                b = dup2(w0.x); a01[0]=ff2(p01[0],b,a01[0]); a23[0]=ff2(p23[0],b,a23[0]);
                b = dup2(w0.y); a01[0]=ff2(p01[1],b,a01[0]); a23[0]=ff2(p23[1],b,a23[0]);
                b = dup2(w0.z); a01[0]=ff2(p01[2],b,a01[0]); a23[0]=ff2(p23[2],b,a23[0]);
                b = dup2(w0.w); a01[0]=ff2(p01[3],b,a01[0]); a23[0]=ff2(p23[3],b,a23[0]);
                b = dup2(w1.x); a01[1]=ff2(p01[0],b,a01[1]); a23[1]=ff2(p23[0],b,a23[1]);
                b = dup2(w1.y); a01[1]=ff2(p01[1],b,a01[1]); a23[1]=ff2(p23[1],b,a23[1]);
                b = dup2(w1.z); a01[1]=ff2(p01[2],b,a01[1]); a23[1]=ff2(p23[2],b,a23[1]);
                b = dup2(w1.w); a01[1]=ff2(p01[3],b,a01[1]); a23[1]=ff2(p23[3],b,a23[1]);
                b = dup2(w2.x); a01[2]=ff2(p01[0],b,a01[2]); a23[2]=ff2(p23[0],b,a23[2]);
                b = dup2(w2.y); a01[2]=ff2(p01[1],b,a01[2]); a23[2]=ff2(p23[1],b,a23[2]);
                b = dup2(w2.z); a01[2]=ff2(p01[2],b,a01[2]); a23[2]=ff2(p23[2],b,a23[2]);
                b = dup2(w2.w); a01[2]=ff2(p01[3],b,a01[2]); a23[2]=ff2(p23[3],b,a23[2]);
            }
#pragma unroll
            for (int j = 0; j < 3; j++) {
                int o = tid + j * 256;
                if (o < 576) {
                    float bia = gru_bih[o];
                    sgi[0][o] = lo2(a01[j]) + bia;
                    sgi[1][o] = hi2(a01[j]) + bia;
                    sgi[2][o] = lo2(a23[j]) + bia;
                    sgi[3][o] = hi2(a23[j]) + bia;
                }
            }
        }
        __syncthreads();

#pragma unroll
        for (int ii = 0; ii < 3; ii++) {
            int idx = tid + ii * 256;
            int r = idx / 192, ch = idx - r * 192;
            float rg = sigf(sgi[r][ch] + sgh[r][ch]);
            float zg = sigf(sgi[r][192 + ch] + sgh[r][192 + ch]);
            float ng = tanhf(sgi[r][384 + ch] + rg * sgh[r][384 + ch]);
            float hr = sSt[ch][r];
            spre[r][ch] = (1.0f - zg) * ng + zg * hr;
        }
        __syncthreads();

        if (wid < 4) {
            int r = wid, row = r0 + r;
            float v[6], sum = 0.0f;
#pragma unroll
            for (int j = 0; j < 6; j++) { v[j] = spre[r][j * 32 + lane]; sum += v[j]; }
            sum = warp_sum(sum);
            float mean = sum * (1.0f / H_);
            float var = 0.0f;
#pragma unroll
            for (int j = 0; j < 6; j++) { float d = v[j] - mean; var = fmaf(d, d, var); }
            var = warp_sum(var) * (1.0f / H_);
            float inv = rsqrtf(var + 1e-5f);

            float p0 = 0.0f, p1 = 0.0f;
#pragma unroll
            for (int j = 0; j < 6; j++) {
                int ch = j * 32 + lane;
                float hn = (v[j] - mean) * inv * roll_ln_w[ch] + roll_ln_b[ch];
                sSt[ch][r] = hn;
                p0 = fmaf(hn, fc_rp_r_w[ch], p0);
                p1 = fmaf(hn, fc_rp_r_w[H_ + ch], p1);
            }
            p0 = warp_sum(p0);
            p1 = warp_sum(p1);
            float rho = 1.25f * sigf(p0 + fc_rp_r_b[0]);
            float phi = PI_ * tanhf(p1 + fc_rp_r_b[1]);
            float s, c;
            sincosf(phi, &s, &c);
            float cur = sSt[192 + lane][r];
            float partner = __shfl_xor_sync(0xffffffffu, cur, 16);
            float nv = (lane < 16) ? rho * (c * cur - s * partner)
                                   : rho * (s * partner + c * cur);
            sSt[192 + lane][r] = nv;
            out[((size_t)row * w_out + step) * D_ + lane] = nv;
        }
        __syncthreads();
    }
}

// -----------------------------------------------------------------------------
extern "C" void kernel_launch(void* const* d_in, const int* in_sizes, int n_in,
                              void* d_out, int out_size) {
    const float* x_in      = (const float*)d_in[0];
    const float* inp_w     = (const float*)d_in[1];
    const float* inp_b     = (const float*)d_in[2];
    const float* b_dw_w    = (const float*)d_in[3];
    const float* b_dw_b    = (const float*)d_in[4];
    const float* b_ln_w    = (const float*)d_in[5];
    const float* b_ln_b    = (const float*)d_in[6];
    const float* b_pw1_w   = (const float*)d_in[7];
    const float* b_pw1_b   = (const float*)d_in[8];
    const float* b_grn_g   = (const float*)d_in[9];
    const float* b_grn_b   = (const float*)d_in[10];
    const float* b_pw2_w   = (const float*)d_in[11];
    const float* b_pw2_b   = (const float*)d_in[12];
    const float* out_ln_w  = (const float*)d_in[13];
    const float* out_ln_b  = (const float*)d_in[14];
    const float* fc_rp_w   = (const float*)d_in[15];
    const float* fc_rp_b   = (const float*)d_in[16];
    const float* fc_gain_w = (const float*)d_in[17];
    const float* fc_gain_b = (const float*)d_in[18];
    const float* roll_in_w = (const float*)d_in[19];
    const float* roll_in_b = (const float*)d_in[20];
    const float* gru_wih   = (const float*)d_in[21];
    const float* gru_whh   = (const float*)d_in[22];
    const float* gru_bih   = (const float*)d_in[23];
    const float* gru_bhh   = (const float*)d_in[24];
    const float* roll_ln_w = (const float*)d_in[25];
    const float* roll_ln_b = (const float*)d_in[26];
    const float* fc_rp_r_w = (const float*)d_in[27];
    const float* fc_rp_r_b = (const float*)d_in[28];

    float* out = (float*)d_out;
    const int w_out = out_size / (B_ * D_);

    constexpr int SMX = 16384 * 2 + 64 * 128 * 2 + 2048;   // 51200
    cudaFuncSetAttribute(k_mma<1>, cudaFuncAttributeMaxDynamicSharedMemorySize, SMX);
    cudaFuncSetAttribute(k_mma<2>, cudaFuncAttributeMaxDynamicSharedMemorySize, SMX);

    // 0. pack rollout weights + pw1 split + pw2 effective bias
    k_pack<<<(431232 + 255) / 256, 256>>>(
        roll_in_w, roll_in_b, gru_whh, gru_bhh, gru_wih,
        b_pw1_w, b_pw2_w, b_pw2_b, b_grn_b);

    // 1. input projection with features on the fly: x_in -> g_h
    {
        dim3 grid(H_ / 64, BQ_ / 128);
        k_gemm3<<<grid, 256>>>(inp_w, inp_b, INC_, H_, x_in);
    }

    // 2. ConvNeXt blocks
    for (int blk = 0; blk < 2; blk++) {
        {
            dim3 grid(Q_ / 16, B_);
            k_conv<<<grid, 256>>>(b_dw_w + blk * H_ * 9, b_dw_b + blk * H_,
                                  b_ln_w + blk * H_,     b_ln_b + blk * H_);
        }
        {
            // pw1 + GELU + GRN partials -> split y1
            dim3 grid(HID_ / 64, BQ_ / 128);
            k_mma<1><<<grid, 256, SMX>>>(
                blk, b_pw1_b + blk * HID_, H_, HID_, nullptr, nullptr);
        }
        {
            // pw2: W scaled by GRN in staging, bias2, residual -> g_h
            dim3 grid(H_ / 64, BQ_ / 128);
            k_mma<2><<<grid, 256, SMX>>>(
                blk, nullptr, HID_, H_,
                b_pw2_w + (size_t)blk * H_ * HID_, b_grn_g + blk * HID_);
        }
    }

    // 3. out-LN + rho/phi/gain
    k_rpg<<<BQ_ / 8, 256>>>(out_ln_w, out_ln_b, fc_rp_w, fc_rp_b,
                            fc_gain_w, fc_gain_b);

    // 4. Kalman scan
    k_scan<<<B_ / 4, 128>>>(x_in);

    // 5. persistent GRU rollout
    k_roll<<<B_ / 4, 256>>>(gru_bih, roll_ln_w, roll_ln_b,
                            fc_rp_r_w, fc_rp_r_b, out, w_out);
}

// round 14
// speedup vs baseline: 1.0891x; 1.0891x over previous
#include <cuda_runtime.h>
#include <cuda_fp16.h>
#include <math.h>
#include <stdint.h>

constexpr int B_   = 256;
constexpr int Q_   = 512;
constexpr int D_   = 32;
constexpr int H_   = 192;
constexpr int HID_ = 384;
constexpr int INC_ = 96;     // 3*D
constexpr int BQ_  = B_ * Q_;
constexpr float PI_ = 3.14159265358979323846f;
constexpr float SPLIT_SCALE = 2048.0f;        // 2^11
constexpr float SPLIT_INV   = 1.0f / 2048.0f;

typedef unsigned long long ull;

// ------------------------- scratch (device globals) ------------------------
__device__ float g_h   [(size_t)BQ_ * H_];
__device__ float g_part[4 * B_ * HID_];
__device__ float g_scale[B_ * HID_];
__device__ float g_rp  [BQ_ * 2];
__device__ float g_gain[(size_t)BQ_ * D_];
__device__ float g_hr  [B_ * H_];
__device__ float g_curr[B_ * D_];
// conv output + pw1 output as fp16 hi / scaled-lo split
__device__ __half g_yh [(size_t)BQ_ * H_];
__device__ __half g_yl [(size_t)BQ_ * H_];
__device__ __half g_y1h[(size_t)BQ_ * HID_];
__device__ __half g_y1l[(size_t)BQ_ * HID_];
// pre-split pw1 weights (fp16 hi / scaled-lo), [blk][n][k]
__device__ __half g_w1h[2 * HID_ * H_];
__device__ __half g_w1l[2 * HID_ * H_];
// per-batch GRN-scaled split pw2 weights: [b][n][k]
__device__ __half g_w2bh[(size_t)B_ * H_ * HID_];
__device__ __half g_w2bl[(size_t)B_ * H_ * HID_];
// pw2 effective bias: pw2_b[n] + sum_k grnb[k]*W2[n,k]
__device__ float g_bias2[2 * H_];
// rollout weights, float4-packed
__device__ float g_pA4 [56 * 768 * 4];
__device__ float g_bA  [768];
__device__ float g_wih4[48 * 576 * 4];

__device__ __forceinline__ float sigf(float x) { return 1.0f / (1.0f + expf(-x)); }

__device__ __forceinline__ float warp_sum(float v) {
#pragma unroll
    for (int o = 16; o > 0; o >>= 1) v += __shfl_xor_sync(0xffffffffu, v, o);
    return v;
}

// packed f32x2 helpers
__device__ __forceinline__ ull ff2(ull a, ull b, ull c) {
    ull d;
    asm("fma.rn.f32x2 %0, %1, %2, %3;" : "=l"(d) : "l"(a), "l"(b), "l"(c));
    return d;
}
__device__ __forceinline__ ull dup2(float x) {
    ull d;
    unsigned xb = __float_as_uint(x);
    asm("mov.b64 %0, {%1, %1};" : "=l"(d) : "r"(xb));
    return d;
}
__device__ __forceinline__ float lo2(ull v) { return __uint_as_float((unsigned)v); }
__device__ __forceinline__ float hi2(ull v) { return __uint_as_float((unsigned)(v >> 32)); }

// ------------------------- mma.sync helpers ---------------------------------
__device__ __forceinline__ uint32_t smem_u32(const void* p) {
    uint32_t a;
    asm("{ .reg .u64 t; cvta.to.shared.u64 t, %1; cvt.u32.u64 %0, t; }" : "=r"(a) : "l"(p));
    return a;
}
__device__ __forceinline__ void ldm_x4(uint32_t& r0, uint32_t& r1, uint32_t& r2, uint32_t& r3,
                                       uint32_t addr) {
    asm volatile("ldmatrix.sync.aligned.m8n8.x4.shared.b16 {%0,%1,%2,%3}, [%4];"
                 : "=r"(r0), "=r"(r1), "=r"(r2), "=r"(r3) : "r"(addr));
}
__device__ __forceinline__ void mma_f16(float* d, const uint32_t* a,
                                        uint32_t b0, uint32_t b1) {
    asm volatile(
        "mma.sync.aligned.m16n8k16.row.col.f32.f16.f16.f32 "
        "{%0,%1,%2,%3}, {%4,%5,%6,%7}, {%8,%9}, {%0,%1,%2,%3};"
        : "+f"(d[0]), "+f"(d[1]), "+f"(d[2]), "+f"(d[3])
        : "r"(a[0]), "r"(a[1]), "r"(a[2]), "r"(a[3]), "r"(b0), "r"(b1));
}
__device__ __forceinline__ void cpa16(uint32_t saddr, const void* gptr) {
    asm volatile("cp.async.cg.shared.global [%0], [%1], 16;"
                 :: "r"(saddr), "l"(__cvta_generic_to_global(gptr)) : "memory");
}
#define CP_COMMIT() asm volatile("cp.async.commit_group;" ::: "memory")
#define CP_WAIT0()  asm volatile("cp.async.wait_group 0;" ::: "memory")

__device__ __forceinline__ uint32_t swz(int row, int byte) {
    return (uint32_t)(row * 128 + (byte ^ ((row & 7) << 4)));
}
__device__ __forceinline__ float geluf(float v) {
    return 0.5f * v * (1.0f + erff(v * 0.70710678118654752f));
}
// scaled split: hi = fp16(v), lo = fp16((v - hi) * 2^11)
__device__ __forceinline__ void split16(float v, __half& hi, __half& lo) {
    hi = __float2half(v);
    lo = __float2half((v - __half2float(hi)) * SPLIT_SCALE);
}

// ------------------------- tensor-core fp16 full-split GEMM -----------------
// acch += Ah*Wh ; accl += Ah*Wl' + Al'*Wh ; acc2 += Al'*Wl'
// result = acch + (accl + acc2/2^11)/2^11
// MODE 1: A = g_yh/l, W = g_w1h/l; out = GELU(..)+bias -> g_y1h/l + GRN partials
// MODE 2: A = g_y1h/l; W = g_w2bh/l (per-batch pre-scaled/split);
//         out = .. + g_bias2 + residual -> g_h.
// Both: BN=64, CTA 128x64, 8 warps 4x2, warp tile 32x32, cp.async 2-stage.
// smem: AH(s)=s*16384; AL(s)=32768+s*16384; WH(s)=65536+s*8192;
//       WL(s)=81920+s*8192; AUX=98304 (1KB)
template <int MODE>
__global__ __launch_bounds__(256) void k_mma(
    int blk, const float* __restrict__ bias, int K, int N)
{
    extern __shared__ char smem[];
    constexpr int NT = 4;

    const uint32_t sb = smem_u32(smem);
    const int tid = threadIdx.x;
    const int wid = tid >> 5, lane = tid & 31;
    const int g = lane >> 2, t = lane & 3;
    const int quad = lane >> 3, lr = lane & 7;
    const int wrow = wid & 3;
    const int wcol = wid >> 2;
    const int m0 = blockIdx.y * 128;
    const int n0 = blockIdx.x * 64;
    const int b  = m0 >> 9;

    const __half *Ah, *Al, *Wh, *Wl;
    if (MODE == 1) {
        Ah = g_yh; Al = g_yl;
        Wh = g_w1h + (size_t)blk * HID_ * H_;
        Wl = g_w1l + (size_t)blk * HID_ * H_;
    } else {
        Ah = g_y1h; Al = g_y1l;
        Wh = g_w2bh + (size_t)b * H_ * HID_;
        Wl = g_w2bl + (size_t)b * H_ * HID_;
    }

    auto issue = [&](int kc, int s) {
        uint32_t aH = sb + s * 16384;
        uint32_t aL = sb + 32768 + s * 16384;
        uint32_t wH = sb + 65536 + s * 8192;
        uint32_t wL = sb + 81920 + s * 8192;
#pragma unroll
        for (int it = 0; it < 4; it++) {
            int id = tid + it * 256;            // 1024 16B chunks (A)
            int r = id >> 3, k8 = (id & 7) * 8;
            uint32_t off = swz(r, k8 * 2);
            size_t src = (size_t)(m0 + r) * K + kc * 64 + k8;
            cpa16(aH + off, Ah + src);
            cpa16(aL + off, Al + src);
        }
#pragma unroll
        for (int it = 0; it < 2; it++) {
            int id = tid + it * 256;            // 512 16B chunks (W)
            int r = id >> 3, k8 = (id & 7) * 8;
            uint32_t off = swz(r, k8 * 2);
            size_t src = (size_t)(n0 + r) * K + kc * 64 + k8;
            cpa16(wH + off, Wh + src);
            cpa16(wL + off, Wl + src);
        }
        CP_COMMIT();
    };

    float acch[2][NT][4], accl[2][NT][4], acc2[2][NT][4];
#pragma unroll
    for (int mt = 0; mt < 2; mt++)
#pragma unroll
        for (int nt = 0; nt < NT; nt++)
#pragma unroll
            for (int j = 0; j < 4; j++) {
                acch[mt][nt][j] = 0.0f; accl[mt][nt][j] = 0.0f; acc2[mt][nt][j] = 0.0f;
            }

    const int nchunks = K >> 6;
    issue(0, 0);
    for (int kc = 0; kc < nchunks; kc++) {
        CP_WAIT0();
        __syncthreads();
        if (kc + 1 < nchunks) issue(kc + 1, (kc + 1) & 1);

        const int s = kc & 1;
        const uint32_t aHb = sb + s * 16384;
        const uint32_t aLb = sb + 32768 + s * 16384;
        const uint32_t wHb = sb + 65536 + s * 8192;
        const uint32_t wLb = sb + 81920 + s * 8192;

#pragma unroll
        for (int ks = 0; ks < 4; ks++) {
            uint32_t ah[2][4], al[2][4];
#pragma unroll
            for (int mt = 0; mt < 2; mt++) {
                int arow = wrow * 32 + mt * 16 + (quad & 1) * 8 + lr;
                int abyte = ks * 32 + (quad >> 1) * 16;
                uint32_t aoff = swz(arow, abyte);
                ldm_x4(ah[mt][0], ah[mt][1], ah[mt][2], ah[mt][3], aHb + aoff);
                ldm_x4(al[mt][0], al[mt][1], al[mt][2], al[mt][3], aLb + aoff);
            }
#pragma unroll
            for (int np = 0; np < 2; np++) {
                int brow = wcol * 32 + np * 16 + (quad >> 1) * 8 + lr;
                int bbyte = ks * 32 + (quad & 1) * 16;
                uint32_t boff = swz(brow, bbyte);
                uint32_t bh[4], bl[4];
                ldm_x4(bh[0], bh[1], bh[2], bh[3], wHb + boff);
                ldm_x4(bl[0], bl[1], bl[2], bl[3], wLb + boff);
#pragma unroll
                for (int mt = 0; mt < 2; mt++) {
                    mma_f16(acch[mt][np * 2 + 0], ah[mt], bh[0], bh[1]);
                    mma_f16(accl[mt][np * 2 + 0], ah[mt], bl[0], bl[1]);
                    mma_f16(accl[mt][np * 2 + 0], al[mt], bh[0], bh[1]);
                    mma_f16(acc2[mt][np * 2 + 0], al[mt], bl[0], bl[1]);
                    mma_f16(acch[mt][np * 2 + 1], ah[mt], bh[2], bh[3]);
                    mma_f16(accl[mt][np * 2 + 1], ah[mt], bl[2], bl[3]);
                    mma_f16(accl[mt][np * 2 + 1], al[mt], bh[2], bh[3]);
                    mma_f16(acc2[mt][np * 2 + 1], al[mt], bl[2], bl[3]);
                }
            }
        }
        __syncthreads();
    }

    // ---- epilogue ----
    float* saux = reinterpret_cast<float*>(smem + 98304);
    float s2[NT][2];
    if (MODE == 1) {
#pragma unroll
        for (int nt = 0; nt < NT; nt++) { s2[nt][0] = 0.0f; s2[nt][1] = 0.0f; }
    }

#pragma unroll
    for (int mt = 0; mt < 2; mt++) {
#pragma unroll
        for (int h = 0; h < 2; h++) {
            int row = m0 + wrow * 32 + mt * 16 + h * 8 + g;
#pragma unroll
            for (int nt = 0; nt < NT; nt++) {
                int col = n0 + wcol * 32 + nt * 8 + 2 * t;
                float bb0, bb1;
                if (MODE == 1) { bb0 = bias[col]; bb1 = bias[col + 1]; }
                else { bb0 = g_bias2[blk * H_ + col]; bb1 = g_bias2[blk * H_ + col + 1]; }
                float c0 = fmaf(acc2[mt][nt][h * 2 + 0], SPLIT_INV, accl[mt][nt][h * 2 + 0]);
                float c1 = fmaf(acc2[mt][nt][h * 2 + 1], SPLIT_INV, accl[mt][nt][h * 2 + 1]);
                float f0 = fmaf(c0, SPLIT_INV, acch[mt][nt][h * 2 + 0]) + bb0;
                float f1 = fmaf(c1, SPLIT_INV, acch[mt][nt][h * 2 + 1]) + bb1;
                if (MODE == 1) {
                    f0 = geluf(f0); f1 = geluf(f1);
                    s2[nt][0] = fmaf(f0, f0, s2[nt][0]);
                    s2[nt][1] = fmaf(f1, f1, s2[nt][1]);
                    __half h0, l0, h1, l1;
                    split16(f0, h0, l0); split16(f1, h1, l1);
                    *reinterpret_cast<__half2*>(g_y1h + (size_t)row * N + col) =
                        __halves2half2(h0, h1);
                    *reinterpret_cast<__half2*>(g_y1l + (size_t)row * N + col) =
                        __halves2half2(l0, l1);
                } else {
                    float2 r = *reinterpret_cast<const float2*>(g_h + (size_t)row * N + col);
                    f0 += r.x; f1 += r.y;
                    float2 o = make_float2(f0, f1);
                    *reinterpret_cast<float2*>(g_h + (size_t)row * N + col) = o;
                }
            }
        }
    }

    if (MODE == 1) {
#pragma unroll
        for (int nt = 0; nt < NT; nt++) {
#pragma unroll
            for (int j = 0; j < 2; j++) {
                float v = s2[nt][j];
                v += __shfl_xor_sync(0xffffffffu, v, 4);
                v += __shfl_xor_sync(0xffffffffu, v, 8);
                v += __shfl_xor_sync(0xffffffffu, v, 16);
                if (g == 0)
                    saux[wrow * 64 + wcol * 32 + nt * 8 + 2 * t + j] = v;
            }
        }
        __syncthreads();
        if (tid < 64) {
            float s = saux[tid] + saux[64 + tid] + saux[128 + tid] + saux[192 + tid];
            int quarter = (m0 >> 7) & 3;
            g_part[(quarter * B_ + b) * HID_ + n0 + tid] = s;
        }
    }
}

// ------------------------- GRN scale from partials ---------------------------
__global__ void k_grn2(const float* __restrict__ grn_g) {
    __shared__ float red[HID_];
    int b = blockIdx.x, tid = threadIdx.x;
    float g = sqrtf(g_part[b * HID_ + tid] +
                    g_part[(B_ + b) * HID_ + tid] +
                    g_part[(2 * B_ + b) * HID_ + tid] +
                    g_part[(3 * B_ + b) * HID_ + tid]);
    red[tid] = g;
    __syncthreads();
    if (tid < 128) red[tid] += red[tid + 256];
    __syncthreads();
    for (int s = 128; s > 0; s >>= 1) {
        if (tid < s) red[tid] += red[tid + s];
        __syncthreads();
    }
    float mean = red[0] * (1.0f / HID_);
    float nx = g / (mean + 1e-6f);
    g_scale[b * HID_ + tid] = 1.0f + grn_g[tid] * nx;
}

// ------------------------- per-batch scaled-split W2 -------------------------
__global__ __launch_bounds__(256) void k_wsplit(const float* __restrict__ W2) {
    __shared__ float ss[HID_];
    const int b = blockIdx.x;
    const int tid = threadIdx.x;
    for (int i = tid; i < HID_; i += 256) ss[i] = g_scale[b * HID_ + i];
    __syncthreads();
    // 192 rows x 384 cols = 18432 float4 groups
    for (int i = tid; i < 18432; i += 256) {
        int n  = i / 96;
        int c4 = (i % 96) * 4;
        float4 w = *reinterpret_cast<const float4*>(W2 + (size_t)n * HID_ + c4);
        w.x *= ss[c4 + 0]; w.y *= ss[c4 + 1];
        w.z *= ss[c4 + 2]; w.w *= ss[c4 + 3];
        __half h0, l0, h1, l1, h2, l2, h3, l3;
        split16(w.x, h0, l0); split16(w.y, h1, l1);
        split16(w.z, h2, l2); split16(w.w, h3, l3);
        size_t dst = ((size_t)b * H_ + n) * HID_ + c4;
        *reinterpret_cast<__half2*>(g_w2bh + dst)     = __halves2half2(h0, h1);
        *reinterpret_cast<__half2*>(g_w2bh + dst + 2) = __halves2half2(h2, h3);
        *reinterpret_cast<__half2*>(g_w2bl + dst)     = __halves2half2(l0, l1);
        *reinterpret_cast<__half2*>(g_w2bl + dst + 2) = __halves2half2(l2, l3);
    }
}

// ------------------------- scalar SGEMM for input projection ----------------
__global__ __launch_bounds__(256) void k_gemm3(
    const float* __restrict__ W, const float* __restrict__ bias,
    int K, int N, const float* __restrict__ x_in)
{
    constexpr int BM = 128, BN = 64, BK = 16, TN = 4;
    constexpr int AS = 132, BS = BN + 4;
    __shared__ float As[BK * AS];
    __shared__ float Bs[BK * BS];

    const int m0 = blockIdx.y * BM;
    const int n0 = blockIdx.x * BN;
    const int tid = threadIdx.x;
    const int tx = tid & 15;
    const int ty = tid >> 4;

    ull acc[4][TN];
#pragma unroll
    for (int p = 0; p < 4; p++)
#pragma unroll
        for (int j = 0; j < TN; j++) acc[p][j] = 0ull;

    for (int k0 = 0; k0 < K; k0 += BK) {
#pragma unroll
        for (int it = 0; it < 2; it++) {
            int f = tid + it * 256;
            int row = f >> 2;
            int k4  = f & 3;
            int grow = m0 + row;
            int gk = k0 + k4 * 4;
            int t = grow & (Q_ - 1);
            int g = gk >> 5;
            int d = gk & 31;
            const float* xr = x_in + (size_t)grow * D_ + d;
            float4 x0 = *reinterpret_cast<const float4*>(xr);
            float4 v;
            if (g == 0) {
                v = x0;
            } else {
                float4 x1 = (t >= 1) ? *reinterpret_cast<const float4*>(xr - D_) : x0;
                if (g == 1) {
                    v = make_float4(x0.x - x1.x, x0.y - x1.y, x0.z - x1.z, x0.w - x1.w);
                } else {
                    float4 x2 = (t >= 2) ? *reinterpret_cast<const float4*>(xr - 2 * D_) : x1;
                    v = make_float4(x0.x - 2.0f * x1.x + x2.x,
                                    x0.y - 2.0f * x1.y + x2.y,
                                    x0.z - 2.0f * x1.z + x2.z,
                                    x0.w - 2.0f * x1.w + x2.w);
                }
            }
            As[(k4 * 4 + 0) * AS + row] = v.x;
            As[(k4 * 4 + 1) * AS + row] = v.y;
            As[(k4 * 4 + 2) * AS + row] = v.z;
            As[(k4 * 4 + 3) * AS + row] = v.w;
        }
        {
            int row = tid >> 2;
            int k4  = tid & 3;
            float4 v = *reinterpret_cast<const float4*>(W + (size_t)(n0 + row) * K + (k0 + k4 * 4));
            Bs[(k4 * 4 + 0) * BS + row] = v.x;
            Bs[(k4 * 4 + 1) * BS + row] = v.y;
            Bs[(k4 * 4 + 2) * BS + row] = v.z;
            Bs[(k4 * 4 + 3) * BS + row] = v.w;
        }
        __syncthreads();

#pragma unroll
        for (int kk = 0; kk < BK; kk++) {
            const ulonglong2* a2 = reinterpret_cast<const ulonglong2*>(&As[kk * AS + ty * 8]);
            ulonglong2 q0 = a2[0], q1 = a2[1];
            ull ap[4];
            ap[0] = q0.x; ap[1] = q0.y; ap[2] = q1.x; ap[3] = q1.y;
            float4 tb = *reinterpret_cast<const float4*>(&Bs[kk * BS + tx * TN]);
            ull bd[4];
            bd[0] = dup2(tb.x); bd[1] = dup2(tb.y); bd[2] = dup2(tb.z); bd[3] = dup2(tb.w);
#pragma unroll
            for (int p = 0; p < 4; p++)
#pragma unroll
                for (int j = 0; j < TN; j++)
                    acc[p][j] = ff2(ap[p], bd[j], acc[p][j]);
        }
        __syncthreads();
    }

    float4 bia = *reinterpret_cast<const float4*>(bias + n0 + tx * TN);
#pragma unroll
    for (int p = 0; p < 4; p++) {
#pragma unroll
        for (int hf = 0; hf < 2; hf++) {
            int row = m0 + ty * 8 + p * 2 + hf;
            float4 o;
            o.x = (hf ? hi2(acc[p][0]) : lo2(acc[p][0])) + bia.x;
            o.y = (hf ? hi2(acc[p][1]) : lo2(acc[p][1])) + bia.y;
            o.z = (hf ? hi2(acc[p][2]) : lo2(acc[p][2])) + bia.z;
            o.w = (hf ? hi2(acc[p][3]) : lo2(acc[p][3])) + bia.w;
            *reinterpret_cast<float4*>(g_h + (size_t)row * N + n0 + tx * TN) = o;
        }
    }
}

// ------------------------- depthwise conv + LN -> fp16 split ----------------
__global__ __launch_bounds__(256) void k_conv(
    const float* __restrict__ dw_w, const float* __restrict__ dw_b,
    const float* __restrict__ ln_w, const float* __restrict__ ln_b)
{
    __shared__ float s_in[24][H_];
    __shared__ float s_out[16][H_];
    __shared__ float s_w[H_ * 9];
    __shared__ float s_b[H_];

    const int b  = blockIdx.y;
    const int t0 = blockIdx.x * 16;
    const int tid = threadIdx.x;

    for (int i = tid; i < H_ * 9; i += 256) s_w[i] = dw_w[i];
    for (int i = tid; i < H_; i += 256) s_b[i] = dw_b[i];
    for (int i = tid; i < 24 * H_; i += 256) {
        int r = i / H_, ch = i % H_;
        int t = t0 + r - 4;
        t = min(max(t, 0), Q_ - 1);
        s_in[r][ch] = g_h[((size_t)b * Q_ + t) * H_ + ch];
    }
    __syncthreads();

    for (int i = tid; i < 16 * H_; i += 256) {
        int r = i / H_, ch = i % H_;
        float acc = s_b[ch];
#pragma unroll
        for (int k = 0; k < 9; k++) acc = fmaf(s_in[r + k][ch], s_w[ch * 9 + k], acc);
        s_out[r][ch] = acc;
    }
    __syncthreads();

    const int wid = tid >> 5, lane = tid & 31;
#pragma unroll
    for (int rr = 0; rr < 2; rr++) {
        int r = wid * 2 + rr;
        float v[6], sum = 0.0f;
#pragma unroll
        for (int j = 0; j < 6; j++) { v[j] = s_out[r][j * 32 + lane]; sum += v[j]; }
        sum = warp_sum(sum);
        float mean = sum * (1.0f / H_);
        float var = 0.0f;
#pragma unroll
        for (int j = 0; j < 6; j++) { float d = v[j] - mean; var = fmaf(d, d, var); }
        var = warp_sum(var) * (1.0f / H_);
        float inv = rsqrtf(var + 1e-5f);
        size_t base = ((size_t)b * Q_ + t0 + r) * H_;
#pragma unroll
        for (int j = 0; j < 6; j++) {
            int ch = j * 32 + lane;
            float val = (v[j] - mean) * inv * ln_w[ch] + ln_b[ch];
            __half hi, lo;
            split16(val, hi, lo);
            g_yh[base + ch] = hi;
            g_yl[base + ch] = lo;
        }
    }
}

// ------------------------- out-LN + rho/phi/gain -----------------------------
__global__ __launch_bounds__(256) void k_rpg(
    const float* __restrict__ out_ln_w, const float* __restrict__ out_ln_b,
    const float* __restrict__ fc_rp_w, const float* __restrict__ fc_rp_b,
    const float* __restrict__ fc_gain_w, const float* __restrict__ fc_gain_b)
{
    const int wid = threadIdx.x >> 5, lane = threadIdx.x & 31;
    const int row = blockIdx.x * 8 + wid;
    const float* hp = g_h + (size_t)row * H_;

    float v[6], sum = 0.0f;
#pragma unroll
    for (int j = 0; j < 6; j++) { v[j] = hp[j * 32 + lane]; sum += v[j]; }
    sum = warp_sum(sum);
    float mean = sum * (1.0f / H_);
    float var = 0.0f;
#pragma unroll
    for (int j = 0; j < 6; j++) { float d = v[j] - mean; var = fmaf(d, d, var); }
    var = warp_sum(var) * (1.0f / H_);
    float inv = rsqrtf(var + 1e-5f);

    float hn[6];
#pragma unroll
    for (int j = 0; j < 6; j++) {
        int ch = j * 32 + lane;
        hn[j] = (v[j] - mean) * inv * out_ln_w[ch] + out_ln_b[ch];
    }

    int t = row & (Q_ - 1), b = row >> 9;
    if (t == Q_ - 1) {
#pragma unroll
        for (int j = 0; j < 6; j++) g_hr[b * H_ + j * 32 + lane] = hn[j];
    }

#pragma unroll
    for (int o = 0; o < 2; o++) {
        float a = 0.0f;
#pragma unroll
        for (int j = 0; j < 6; j++) a = fmaf(hn[j], fc_rp_w[o * H_ + j * 32 + lane], a);
        a = warp_sum(a);
        if (lane == 0) {
            float z = a + fc_rp_b[o];
            g_rp[row * 2 + o] = (o == 0) ? 1.25f * sigf(z) : PI_ * tanhf(z);
        }
    }
    for (int d = 0; d < D_; d++) {
        float a = 0.0f;
#pragma unroll
        for (int j = 0; j < 6; j++) a = fmaf(hn[j], fc_gain_w[d * H_ + j * 32 + lane], a);
        a = warp_sum(a);
        if (lane == 0) g_gain[(size_t)row * D_ + d] = sigf(a + fc_gain_b[d]);
    }
}

// ------------------------- Kalman scan ---------------------------------------
__global__ void k_scan(const float* __restrict__ x_in) {
    const int wid = threadIdx.x >> 5, lane = threadIdx.x & 31;
    const int b = blockIdx.x * 4 + wid;
    const int base = b * Q_;

    float x  = x_in[(size_t)base * D_ + lane];
    float2 rp = *reinterpret_cast<const float2*>(g_rp + base * 2);
    float gn = g_gain[(size_t)base * D_ + lane];
    float y  = x;

    for (int t = 0; t < Q_; t++) {
        float2 rp_n = rp; float gn_n = gn, y_n = y;
        if (t + 1 < Q_) {
            rp_n = *reinterpret_cast<const float2*>(g_rp + (base + t + 1) * 2);
            gn_n = g_gain[(size_t)(base + t + 1) * D_ + lane];
            y_n  = x_in[(size_t)(base + t + 1) * D_ + lane];
        }
        float s, c;
        sincosf(rp.y, &s, &c);
        float partner = __shfl_xor_sync(0xffffffffu, x, 16);
        float xp = (lane < 16) ? rp.x * (c * x - s * partner)
                               : rp.x * (s * partner + c * x);
        x = xp + gn * (y - xp);
        rp = rp_n; gn = gn_n; y = y_n;
    }
    g_curr[b * D_ + lane] = x;
}

// ------------------------- packing ------------------------------------------
__global__ void k_pack(const float* __restrict__ roll_in_w, const float* __restrict__ roll_in_b,
                       const float* __restrict__ gru_whh, const float* __restrict__ gru_bhh,
                       const float* __restrict__ gru_wih,
                       const float* __restrict__ b_pw1_w, const float* __restrict__ b_pw2_w,
                       const float* __restrict__ b_pw2_b, const float* __restrict__ b_grn_b)
{
    int i = blockIdx.x * 256 + threadIdx.x;
    constexpr int NA = 56 * 768 * 4;                 // 172032
    constexpr int NB = NA + 768;                     // 172800
    constexpr int NW = NB + 48 * 576 * 4;            // 283392
    constexpr int NW1 = NW + 2 * HID_ * H_;          // 430848 (32-aligned)
    constexpr int NB2 = NW1 + 2 * H_ * 32;           // +12288 warp-per-output
    if (i < NA) {
        int k4 = i / (768 * 4);
        int rem = i % (768 * 4);
        int c = rem >> 2;
        int j = rem & 3;
        int k = 4 * k4 + j;
        float v;
        if (c < 192)      v = roll_in_w[c * 224 + k];
        else if (k < 192) v = gru_whh[(c - 192) * 192 + k];
        else              v = 0.0f;
        g_pA4[i] = v;
    } else if (i < NB) {
        int c = i - NA;
        g_bA[c] = (c < 192) ? roll_in_b[c] : gru_bhh[c - 192];
    } else if (i < NW) {
        int t = i - NB;
        int k4 = t / (576 * 4);
        int rem = t % (576 * 4);
        int o = rem >> 2;
        int j = rem & 3;
        g_wih4[t] = gru_wih[o * 192 + 4 * k4 + j];
    } else if (i < NW1) {
        int j = i - NW;
        __half hi, lo;
        split16(b_pw1_w[j], hi, lo);
        g_w1h[j] = hi;
        g_w1l[j] = lo;
    } else if (i < NB2) {
        int j = i - NW1;
        int out = j >> 5, lane = j & 31;     // out < 384
        int blk = out / H_, n = out % H_;
        const float* w = b_pw2_w + (size_t)blk * H_ * HID_ + (size_t)n * HID_;
        const float* gb = b_grn_b + blk * HID_;
        float s = 0.0f;
        for (int k = lane; k < HID_; k += 32) s = fmaf(gb[k], w[k], s);
        s = warp_sum(s);
        if (lane == 0) g_bias2[out] = s + b_pw2_b[out];
    }
}

// ------------------------- persistent GRU rollout ----------------------------
__global__ __launch_bounds__(256) void k_roll(
    const float* __restrict__ gru_bih,
    const float* __restrict__ roll_ln_w, const float* __restrict__ roll_ln_b,
    const float* __restrict__ fc_rp_r_w, const float* __restrict__ fc_rp_r_b,
    float* __restrict__ out, int w_out)
{
    __shared__ float sSt[224][4];
    __shared__ float sx [192][4];
    __shared__ float sgh[4][576];
    __shared__ float sgi[4][576];
    __shared__ float spre[4][192];

    const int r0 = blockIdx.x * 4;
    const int tid = threadIdx.x;
    const int wid = tid >> 5, lane = tid & 31;

    const float4* pA4  = reinterpret_cast<const float4*>(g_pA4);
    const float4* wih4 = reinterpret_cast<const float4*>(g_wih4);

    for (int i = tid; i < 4 * 224; i += 256) {
        int r = i / 224, k = i % 224;
        sSt[k][r] = (k < 192) ? g_hr[(r0 + r) * H_ + k]
                              : g_curr[(r0 + r) * D_ + (k - 192)];
    }
    __syncthreads();

    for (int step = 0; step < w_out; step++) {
        {
            ull a01[3], a23[3];
#pragma unroll
            for (int j = 0; j < 3; j++) { a01[j] = 0ull; a23[j] = 0ull; }
#pragma unroll 4
            for (int k4 = 0; k4 < 56; k4++) {
                float4 w0 = __ldg(pA4 + k4 * 768 + tid);
                float4 w1 = __ldg(pA4 + k4 * 768 + tid + 256);
                float4 w2 = __ldg(pA4 + k4 * 768 + tid + 512);
                ull p01[4], p23[4];
#pragma unroll
                for (int j = 0; j < 4; j++) {
                    p01[j] = *reinterpret_cast<const ull*>(&sSt[k4 * 4 + j][0]);
                    p23[j] = *reinterpret_cast<const ull*>(&sSt[k4 * 4 + j][2]);
                }
                ull b;
                b = dup2(w0.x); a01[0]=ff2(p01[0],b,a01[0]); a23[0]=ff2(p23[0],b,a23[0]);
                b = dup2(w0.y); a01[0]=ff2(p01[1],b,a01[0]); a23[0]=ff2(p23[1],b,a23[0]);
                b = dup2(w0.z); a01[0]=ff2(p01[2],b,a01[0]); a23[0]=ff2(p23[2],b,a23[0]);
                b = dup2(w0.w); a01[0]=ff2(p01[3],b,a01[0]); a23[0]=ff2(p23[3],b,a23[0]);
                b = dup2(w1.x); a01[1]=ff2(p01[0],b,a01[1]); a23[1]=ff2(p23[0],b,a23[1]);
                b = dup2(w1.y); a01[1]=ff2(p01[1],b,a01[1]); a23[1]=ff2(p23[1],b,a23[1]);
                b = dup2(w1.z); a01[1]=ff2(p01[2],b,a01[1]); a23[1]=ff2(p23[2],b,a23[1]);
                b = dup2(w1.w); a01[1]=ff2(p01[3],b,a01[1]); a23[1]=ff2(p23[3],b,a23[1]);
                b = dup2(w2.x); a01[2]=ff2(p01[0],b,a01[2]); a23[2]=ff2(p23[0],b,a23[2]);
                b = dup2(w2.y); a01[2]=ff2(p01[1],b,a01[2]); a23[2]=ff2(p23[1],b,a23[2]);
                b = dup2(w2.z); a01[2]=ff2(p01[2],b,a01[2]); a23[2]=ff2(p23[2],b,a23[2]);
                b = dup2(w2.w); a01[2]=ff2(p01[3],b,a01[2]); a23[2]=ff2(p23[3],b,a23[2]);
            }
#pragma unroll
            for (int j = 0; j < 3; j++) {
                int c = tid + j * 256;
                float bia = g_bA[c];
                float v0 = lo2(a01[j]) + bia;
                float v1 = hi2(a01[j]) + bia;
                float v2 = lo2(a23[j]) + bia;
                float v3 = hi2(a23[j]) + bia;
                if (c < 192) {
                    sx[c][0] = tanhf(v0); sx[c][1] = tanhf(v1);
                    sx[c][2] = tanhf(v2); sx[c][3] = tanhf(v3);
                } else {
                    int o = c - 192;
                    sgh[0][o] = v0; sgh[1][o] = v1; sgh[2][o] = v2; sgh[3][o] = v3;
                }
            }
        }
        __syncthreads();

        {
            ull a01[3], a23[3];
#pragma unroll
            for (int j = 0; j < 3; j++) { a01[j] = 0ull; a23[j] = 0ull; }
            int o2c = (tid < 64) ? (tid + 512) : 575;
#pragma unroll 4
            for (int k4 = 0; k4 < 48; k4++) {
                float4 w0 = __ldg(wih4 + k4 * 576 + tid);
                float4 w1 = __ldg(wih4 + k4 * 576 + tid + 256);
                float4 w2 = __ldg(wih4 + k4 * 576 + o2c);
                ull p01[4], p23[4];
#pragma unroll
                for (int j = 0; j < 4; j++) {
                    p01[j] = *reinterpret_cast<const ull*>(&sx[k4 * 4 + j][0]);
                    p23[j] = *reinterpret_cast<const ull*>(&sx[k4 * 4 + j][2]);
                }
                ull b;
                b = dup2(w0.x); a01[0]=ff2(p01[0],b,a01[0]); a23[0]=ff2(p23[0],b,a23[0]);
                b = dup2(w0.y); a01[0]=ff2(p01[1],b,a01[0]); a23[0]=ff2(p23[1],b,a23[0]);
                b = dup2(w0.z); a01[0]=ff2(p01[2],b,a01[0]); a23[0]=ff2(p23[2],b,a23[0]);
                b = dup2(w0.w); a01[0]=ff2(p01[3],b,a01[0]); a23[0]=ff2(p23[3],b,a23[0]);
                b = dup2(w1.x); a01[1]=ff2(p01[0],b,a01[1]); a23[1]=ff2(p23[0],b,a23[1]);
                b = dup2(w1.y); a01[1]=ff2(p01[1],b,a01[1]); a23[1]=ff2(p23[1],b,a23[1]);
                b = dup2(w1.z); a01[1]=ff2(p01[2],b,a01[1]); a23[1]=ff2(p23[2],b,a23[1]);
                b = dup2(w1.w); a01[1]=ff2(p01[3],b,a01[1]); a23[1]=ff2(p23[3],b,a23[1]);
                b = dup2(w2.x); a01[2]=ff2(p01[0],b,a01[2]); a23[2]=ff2(p23[0],b,a23[2]);
                b = dup2(w2.y); a01[2]=ff2(p01[1],b,a01[2]); a23[2]=ff2(p23[1],b,a23[2]);
                b = dup2(w2.z); a01[2]=ff2(p01[2],b,a01[2]); a23[2]=ff2(p23[2],b,a23[2]);
                b = dup2(w2.w); a01[2]=ff2(p01[3],b,a01[2]); a23[2]=ff2(p23[3],b,a23[2]);
            }
#pragma unroll
            for (int j = 0; j < 3; j++) {
                int o = tid + j * 256;
                if (o < 576) {
                    float bia = gru_bih[o];
                    sgi[0][o] = lo2(a01[j]) + bia;
                    sgi[1][o] = hi2(a01[j]) + bia;
                    sgi[2][o] = lo2(a23[j]) + bia;
                    sgi[3][o] = hi2(a23[j]) + bia;
                }
            }
        }
        __syncthreads();

#pragma unroll
        for (int ii = 0; ii < 3; ii++) {
            int idx = tid + ii * 256;
            int r = idx / 192, ch = idx - r * 192;
            float rg = sigf(sgi[r][ch] + sgh[r][ch]);
            float zg = sigf(sgi[r][192 + ch] + sgh[r][192 + ch]);
            float ng = tanhf(sgi[r][384 + ch] + rg * sgh[r][384 + ch]);
            float hr = sSt[ch][r];
            spre[r][ch] = (1.0f - zg) * ng + zg * hr;
        }
        __syncthreads();

        if (wid < 4) {
            int r = wid, row = r0 + r;
            float v[6], sum = 0.0f;
#pragma unroll
            for (int j = 0; j < 6; j++) { v[j] = spre[r][j * 32 + lane]; sum += v[j]; }
            sum = warp_sum(sum);
            float mean = sum * (1.0f / H_);
            float var = 0.0f;
#pragma unroll
            for (int j = 0; j < 6; j++) { float d = v[j] - mean; var = fmaf(d, d, var); }
            var = warp_sum(var) * (1.0f / H_);
            float inv = rsqrtf(var + 1e-5f);

            float p0 = 0.0f, p1 = 0.0f;
#pragma unroll
            for (int j = 0; j < 6; j++) {
                int ch = j * 32 + lane;
                float hn = (v[j] - mean) * inv * roll_ln_w[ch] + roll_ln_b[ch];
                sSt[ch][r] = hn;
                p0 = fmaf(hn, fc_rp_r_w[ch], p0);
                p1 = fmaf(hn, fc_rp_r_w[H_ + ch], p1);
            }
            p0 = warp_sum(p0);
            p1 = warp_sum(p1);
            float rho = 1.25f * sigf(p0 + fc_rp_r_b[0]);
            float phi = PI_ * tanhf(p1 + fc_rp_r_b[1]);
            float s, c;
            sincosf(phi, &s, &c);
            float cur = sSt[192 + lane][r];
            float partner = __shfl_xor_sync(0xffffffffu, cur, 16);
            float nv = (lane < 16) ? rho * (c * cur - s * partner)
                                   : rho * (s * partner + c * cur);
            sSt[192 + lane][r] = nv;
            out[((size_t)row * w_out + step) * D_ + lane] = nv;
        }
        __syncthreads();
    }
}

// -----------------------------------------------------------------------------
extern "C" void kernel_launch(void* const* d_in, const int* in_sizes, int n_in,
                              void* d_out, int out_size) {
    const float* x_in      = (const float*)d_in[0];
    const float* inp_w     = (const float*)d_in[1];
    const float* inp_b     = (const float*)d_in[2];
    const float* b_dw_w    = (const float*)d_in[3];
    const float* b_dw_b    = (const float*)d_in[4];
    const float* b_ln_w    = (const float*)d_in[5];
    const float* b_ln_b    = (const float*)d_in[6];
    const float* b_pw1_w   = (const float*)d_in[7];
    const float* b_pw1_b   = (const float*)d_in[8];
    const float* b_grn_g   = (const float*)d_in[9];
    const float* b_grn_b   = (const float*)d_in[10];
    const float* b_pw2_w   = (const float*)d_in[11];
    const float* b_pw2_b   = (const float*)d_in[12];
    const float* out_ln_w  = (const float*)d_in[13];
    const float* out_ln_b  = (const float*)d_in[14];
    const float* fc_rp_w   = (const float*)d_in[15];
    const float* fc_rp_b   = (const float*)d_in[16];
    const float* fc_gain_w = (const float*)d_in[17];
    const float* fc_gain_b = (const float*)d_in[18];
    const float* roll_in_w = (const float*)d_in[19];
    const float* roll_in_b = (const float*)d_in[20];
    const float* gru_wih   = (const float*)d_in[21];
    const float* gru_whh   = (const float*)d_in[22];
    const float* gru_bih   = (const float*)d_in[23];
    const float* gru_bhh   = (const float*)d_in[24];
    const float* roll_ln_w = (const float*)d_in[25];
    const float* roll_ln_b = (const float*)d_in[26];
    const float* fc_rp_r_w = (const float*)d_in[27];
    const float* fc_rp_r_b = (const float*)d_in[28];

    float* out = (float*)d_out;
    const int w_out = out_size / (B_ * D_);

    constexpr int SMX = 98304 + 1024;   // 2-stage A(hi/lo)+W(hi/lo) + aux
    cudaFuncSetAttribute(k_mma<1>, cudaFuncAttributeMaxDynamicSharedMemorySize, SMX);
    cudaFuncSetAttribute(k_mma<2>, cudaFuncAttributeMaxDynamicSharedMemorySize, SMX);

    // 0. pack rollout weights + pw1 split + parallel pw2 effective bias
    k_pack<<<(443136 + 255) / 256, 256>>>(
        roll_in_w, roll_in_b, gru_whh, gru_bhh, gru_wih,
        b_pw1_w, b_pw2_w, b_pw2_b, b_grn_b);

    // 1. input projection with features on the fly: x_in -> g_h
    {
        dim3 grid(H_ / 64, BQ_ / 128);
        k_gemm3<<<grid, 256>>>(inp_w, inp_b, INC_, H_, x_in);
    }

    // 2. ConvNeXt blocks
    for (int blk = 0; blk < 2; blk++) {
        {
            dim3 grid(Q_ / 16, B_);
            k_conv<<<grid, 256>>>(b_dw_w + blk * H_ * 9, b_dw_b + blk * H_,
                                  b_ln_w + blk * H_,     b_ln_b + blk * H_);
        }
        {
            // pw1 + GELU + GRN partials -> split y1   [profile index 3]
            dim3 grid(HID_ / 64, BQ_ / 128);
            k_mma<1><<<grid, 256, SMX>>>(blk, b_pw1_b + blk * HID_, H_, HID_);
        }
        // GRN scale per batch, then per-batch scaled-split W2
        k_grn2<<<B_, HID_>>>(b_grn_g + blk * HID_);
        k_wsplit<<<B_, 256>>>(b_pw2_w + (size_t)blk * H_ * HID_);
        {
            // pw2: pre-scaled W, bias2, residual -> g_h
            dim3 grid(H_ / 64, BQ_ / 128);
            k_mma<2><<<grid, 256, SMX>>>(blk, nullptr, HID_, H_);
        }
    }

    // 3. out-LN + rho/phi/gain
    k_rpg<<<BQ_ / 8, 256>>>(out_ln_w, out_ln_b, fc_rp_w, fc_rp_b,
                            fc_gain_w, fc_gain_b);

    // 4. Kalman scan
    k_scan<<<B_ / 4, 128>>>(x_in);

    // 5. persistent GRU rollout
    k_roll<<<B_ / 4, 256>>>(gru_bih, roll_ln_w, roll_ln_b,
                            fc_rp_r_w, fc_rp_r_b, out, w_out);
}

// round 15
// speedup vs baseline: 1.2171x; 1.1175x over previous
#include <cuda_runtime.h>
#include <cuda_fp16.h>
#include <math.h>
#include <stdint.h>

constexpr int B_   = 256;
constexpr int Q_   = 512;
constexpr int D_   = 32;
constexpr int H_   = 192;
constexpr int HID_ = 384;
constexpr int INC_ = 96;     // 3*D
constexpr int BQ_  = B_ * Q_;
constexpr float PI_ = 3.14159265358979323846f;
constexpr float SPLIT_SCALE = 2048.0f;        // 2^11
constexpr float SPLIT_INV   = 1.0f / 2048.0f;

typedef unsigned long long ull;

// ------------------------- scratch (device globals) ------------------------
__device__ float g_h   [(size_t)BQ_ * H_];
__device__ float g_part[8 * B_ * HID_];      // 8 eighth-tiles per batch
__device__ float g_scale[B_ * HID_];
__device__ float g_rp  [BQ_ * 2];
__device__ float g_gain[(size_t)BQ_ * D_];
__device__ float g_hr  [B_ * H_];
__device__ float g_curr[B_ * D_];
// conv output + pw1 output as fp16 hi / scaled-lo split
__device__ __half g_yh [(size_t)BQ_ * H_];
__device__ __half g_yl [(size_t)BQ_ * H_];
__device__ __half g_y1h[(size_t)BQ_ * HID_];
__device__ __half g_y1l[(size_t)BQ_ * HID_];
// pre-split pw1 weights (fp16 hi / scaled-lo), [blk][n][k]
__device__ __half g_w1h[2 * HID_ * H_];
__device__ __half g_w1l[2 * HID_ * H_];
// per-batch GRN-scaled split pw2 weights: [b][n][k]
__device__ __half g_w2bh[(size_t)B_ * H_ * HID_];
__device__ __half g_w2bl[(size_t)B_ * H_ * HID_];
// pw2 effective bias: pw2_b[n] + sum_k grnb[k]*W2[n,k]
__device__ float g_bias2[2 * H_];
// rollout weights, float4-packed
__device__ float g_pA4 [56 * 768 * 4];
__device__ float g_bA  [768];
__device__ float g_wih4[48 * 576 * 4];

__device__ __forceinline__ float sigf(float x) { return 1.0f / (1.0f + expf(-x)); }

__device__ __forceinline__ float warp_sum(float v) {
#pragma unroll
    for (int o = 16; o > 0; o >>= 1) v += __shfl_xor_sync(0xffffffffu, v, o);
    return v;
}

// packed f32x2 helpers
__device__ __forceinline__ ull ff2(ull a, ull b, ull c) {
    ull d;
    asm("fma.rn.f32x2 %0, %1, %2, %3;" : "=l"(d) : "l"(a), "l"(b), "l"(c));
    return d;
}
__device__ __forceinline__ ull dup2(float x) {
    ull d;
    unsigned xb = __float_as_uint(x);
    asm("mov.b64 %0, {%1, %1};" : "=l"(d) : "r"(xb));
    return d;
}
__device__ __forceinline__ float lo2(ull v) { return __uint_as_float((unsigned)v); }
__device__ __forceinline__ float hi2(ull v) { return __uint_as_float((unsigned)(v >> 32)); }

// ------------------------- mma.sync helpers ---------------------------------
__device__ __forceinline__ uint32_t smem_u32(const void* p) {
    uint32_t a;
    asm("{ .reg .u64 t; cvta.to.shared.u64 t, %1; cvt.u32.u64 %0, t; }" : "=r"(a) : "l"(p));
    return a;
}
__device__ __forceinline__ void ldm_x4(uint32_t& r0, uint32_t& r1, uint32_t& r2, uint32_t& r3,
                                       uint32_t addr) {
    asm volatile("ldmatrix.sync.aligned.m8n8.x4.shared.b16 {%0,%1,%2,%3}, [%4];"
                 : "=r"(r0), "=r"(r1), "=r"(r2), "=r"(r3) : "r"(addr));
}
__device__ __forceinline__ void mma_f16(float* d, const uint32_t* a,
                                        uint32_t b0, uint32_t b1) {
    asm volatile(
        "mma.sync.aligned.m16n8k16.row.col.f32.f16.f16.f32 "
        "{%0,%1,%2,%3}, {%4,%5,%6,%7}, {%8,%9}, {%0,%1,%2,%3};"
        : "+f"(d[0]), "+f"(d[1]), "+f"(d[2]), "+f"(d[3])
        : "r"(a[0]), "r"(a[1]), "r"(a[2]), "r"(a[3]), "r"(b0), "r"(b1));
}
__device__ __forceinline__ void cpa16(uint32_t saddr, const void* gptr) {
    asm volatile("cp.async.cg.shared.global [%0], [%1], 16;"
                 :: "r"(saddr), "l"(__cvta_generic_to_global(gptr)) : "memory");
}
#define CP_COMMIT() asm volatile("cp.async.commit_group;" ::: "memory")
#define CP_WAIT0()  asm volatile("cp.async.wait_group 0;" ::: "memory")

__device__ __forceinline__ uint32_t swz(int row, int byte) {
    return (uint32_t)(row * 128 + (byte ^ ((row & 7) << 4)));
}
__device__ __forceinline__ float geluf(float v) {
    return 0.5f * v * (1.0f + erff(v * 0.70710678118654752f));
}
// scaled split: hi = fp16(v), lo = fp16((v - hi) * 2^11)
__device__ __forceinline__ void split16(float v, __half& hi, __half& lo) {
    hi = __float2half(v);
    lo = __float2half((v - __half2float(hi)) * SPLIT_SCALE);
}

// ------------------------- tensor-core fp16 full-split GEMM -----------------
// acch += Ah*Wh ; accl += Ah*Wl' + Al'*Wh ; acc2 += Al'*Wl'
// result = acch + (accl + acc2/2^11)/2^11
// MODE 1: A = g_yh/l, W = g_w1h/l; out = GELU(..)+bias -> g_y1h/l + GRN partials
// MODE 2: A = g_y1h/l; W = g_w2bh/l; out = .. + g_bias2 + residual -> g_h
// CTA 64x64, 8 warps 4(row)x2(col), warp tile 16x32, cp.async 2-stage.
// smem: AH(s)=s*8192; AL=16384+s*8192; WH=32768+s*8192; WL=49152+s*8192; AUX=65536
template <int MODE>
__global__ __launch_bounds__(256, 2) void k_mma(
    int blk, const float* __restrict__ bias, int K, int N)
{
    extern __shared__ char smem[];
    constexpr int NT = 4;

    const uint32_t sb = smem_u32(smem);
    const int tid = threadIdx.x;
    const int wid = tid >> 5, lane = tid & 31;
    const int g = lane >> 2, t = lane & 3;
    const int quad = lane >> 3, lr = lane & 7;
    const int wrow = wid & 3;
    const int wcol = wid >> 2;
    const int m0 = blockIdx.y * 64;
    const int n0 = blockIdx.x * 64;
    const int b  = m0 >> 9;

    const __half *Ah, *Al, *Wh, *Wl;
    if (MODE == 1) {
        Ah = g_yh; Al = g_yl;
        Wh = g_w1h + (size_t)blk * HID_ * H_;
        Wl = g_w1l + (size_t)blk * HID_ * H_;
    } else {
        Ah = g_y1h; Al = g_y1l;
        Wh = g_w2bh + (size_t)b * H_ * HID_;
        Wl = g_w2bl + (size_t)b * H_ * HID_;
    }

    auto issue = [&](int kc, int s) {
        uint32_t aH = sb + s * 8192;
        uint32_t aL = sb + 16384 + s * 8192;
        uint32_t wH = sb + 32768 + s * 8192;
        uint32_t wL = sb + 49152 + s * 8192;
#pragma unroll
        for (int it = 0; it < 2; it++) {
            int id = tid + it * 256;            // 512 16B chunks (A)
            int r = id >> 3, k8 = (id & 7) * 8;
            uint32_t off = swz(r, k8 * 2);
            size_t src = (size_t)(m0 + r) * K + kc * 64 + k8;
            cpa16(aH + off, Ah + src);
            cpa16(aL + off, Al + src);
        }
#pragma unroll
        for (int it = 0; it < 2; it++) {
            int id = tid + it * 256;            // 512 16B chunks (W)
            int r = id >> 3, k8 = (id & 7) * 8;
            uint32_t off = swz(r, k8 * 2);
            size_t src = (size_t)(n0 + r) * K + kc * 64 + k8;
            cpa16(wH + off, Wh + src);
            cpa16(wL + off, Wl + src);
        }
        CP_COMMIT();
    };

    float acch[NT][4], accl[NT][4], acc2[NT][4];
#pragma unroll
    for (int nt = 0; nt < NT; nt++)
#pragma unroll
        for (int j = 0; j < 4; j++) {
            acch[nt][j] = 0.0f; accl[nt][j] = 0.0f; acc2[nt][j] = 0.0f;
        }

    const int nchunks = K >> 6;
    issue(0, 0);
    for (int kc = 0; kc < nchunks; kc++) {
        CP_WAIT0();
        __syncthreads();
        if (kc + 1 < nchunks) issue(kc + 1, (kc + 1) & 1);

        const int s = kc & 1;
        const uint32_t aHb = sb + s * 8192;
        const uint32_t aLb = sb + 16384 + s * 8192;
        const uint32_t wHb = sb + 32768 + s * 8192;
        const uint32_t wLb = sb + 49152 + s * 8192;

#pragma unroll
        for (int ks = 0; ks < 4; ks++) {
            uint32_t ah[4], al[4];
            {
                int arow = wrow * 16 + (quad & 1) * 8 + lr;
                int abyte = ks * 32 + (quad >> 1) * 16;
                uint32_t aoff = swz(arow, abyte);
                ldm_x4(ah[0], ah[1], ah[2], ah[3], aHb + aoff);
                ldm_x4(al[0], al[1], al[2], al[3], aLb + aoff);
            }
#pragma unroll
            for (int np = 0; np < 2; np++) {
                int brow = wcol * 32 + np * 16 + (quad >> 1) * 8 + lr;
                int bbyte = ks * 32 + (quad & 1) * 16;
                uint32_t boff = swz(brow, bbyte);
                uint32_t bh[4], bl[4];
                ldm_x4(bh[0], bh[1], bh[2], bh[3], wHb + boff);
                ldm_x4(bl[0], bl[1], bl[2], bl[3], wLb + boff);
                mma_f16(acch[np * 2 + 0], ah, bh[0], bh[1]);
                mma_f16(accl[np * 2 + 0], ah, bl[0], bl[1]);
                mma_f16(accl[np * 2 + 0], al, bh[0], bh[1]);
                mma_f16(acc2[np * 2 + 0], al, bl[0], bl[1]);
                mma_f16(acch[np * 2 + 1], ah, bh[2], bh[3]);
                mma_f16(accl[np * 2 + 1], ah, bl[2], bl[3]);
                mma_f16(accl[np * 2 + 1], al, bh[2], bh[3]);
                mma_f16(acc2[np * 2 + 1], al, bl[2], bl[3]);
            }
        }
        __syncthreads();
    }

    // ---- epilogue ----
    float* saux = reinterpret_cast<float*>(smem + 65536);
    float s2[NT][2];
    if (MODE == 1) {
#pragma unroll
        for (int nt = 0; nt < NT; nt++) { s2[nt][0] = 0.0f; s2[nt][1] = 0.0f; }
    }

#pragma unroll
    for (int h = 0; h < 2; h++) {
        int row = m0 + wrow * 16 + h * 8 + g;
#pragma unroll
        for (int nt = 0; nt < NT; nt++) {
            int col = n0 + wcol * 32 + nt * 8 + 2 * t;
            float bb0, bb1;
            if (MODE == 1) { bb0 = bias[col]; bb1 = bias[col + 1]; }
            else { bb0 = g_bias2[blk * H_ + col]; bb1 = g_bias2[blk * H_ + col + 1]; }
            float c0 = fmaf(acc2[nt][h * 2 + 0], SPLIT_INV, accl[nt][h * 2 + 0]);
            float c1 = fmaf(acc2[nt][h * 2 + 1], SPLIT_INV, accl[nt][h * 2 + 1]);
            float f0 = fmaf(c0, SPLIT_INV, acch[nt][h * 2 + 0]) + bb0;
            float f1 = fmaf(c1, SPLIT_INV, acch[nt][h * 2 + 1]) + bb1;
            if (MODE == 1) {
                f0 = geluf(f0); f1 = geluf(f1);
                s2[nt][0] = fmaf(f0, f0, s2[nt][0]);
                s2[nt][1] = fmaf(f1, f1, s2[nt][1]);
                __half h0, l0, h1, l1;
                split16(f0, h0, l0); split16(f1, h1, l1);
                *reinterpret_cast<__half2*>(g_y1h + (size_t)row * N + col) =
                    __halves2half2(h0, h1);
                *reinterpret_cast<__half2*>(g_y1l + (size_t)row * N + col) =
                    __halves2half2(l0, l1);
            } else {
                float2 r = *reinterpret_cast<const float2*>(g_h + (size_t)row * N + col);
                f0 += r.x; f1 += r.y;
                float2 o = make_float2(f0, f1);
                *reinterpret_cast<float2*>(g_h + (size_t)row * N + col) = o;
            }
        }
    }

    if (MODE == 1) {
#pragma unroll
        for (int nt = 0; nt < NT; nt++) {
#pragma unroll
            for (int j = 0; j < 2; j++) {
                float v = s2[nt][j];
                v += __shfl_xor_sync(0xffffffffu, v, 4);
                v += __shfl_xor_sync(0xffffffffu, v, 8);
                v += __shfl_xor_sync(0xffffffffu, v, 16);
                if (g == 0)
                    saux[wrow * 64 + wcol * 32 + nt * 8 + 2 * t + j] = v;
            }
        }
        __syncthreads();
        if (tid < 64) {
            float s = saux[tid] + saux[64 + tid] + saux[128 + tid] + saux[192 + tid];
            int eighth = (m0 >> 6) & 7;
            g_part[(eighth * B_ + b) * HID_ + n0 + tid] = s;
        }
    }
}

// ------------------------- GRN scale from partials (8 slices) ----------------
__global__ void k_grn2(const float* __restrict__ grn_g) {
    __shared__ float red[HID_];
    int b = blockIdx.x, tid = threadIdx.x;
    float acc = 0.0f;
#pragma unroll
    for (int i = 0; i < 8; i++) acc += g_part[(i * B_ + b) * HID_ + tid];
    float g = sqrtf(acc);
    red[tid] = g;
    __syncthreads();
    if (tid < 128) red[tid] += red[tid + 256];
    __syncthreads();
    for (int s = 128; s > 0; s >>= 1) {
        if (tid < s) red[tid] += red[tid + s];
        __syncthreads();
    }
    float mean = red[0] * (1.0f / HID_);
    float nx = g / (mean + 1e-6f);
    g_scale[b * HID_ + tid] = 1.0f + grn_g[tid] * nx;
}

// ------------------------- per-batch scaled-split W2 -------------------------
__global__ __launch_bounds__(256) void k_wsplit(const float* __restrict__ W2) {
    __shared__ float ss[HID_];
    const int b = blockIdx.x;
    const int tid = threadIdx.x;
    for (int i = tid; i < HID_; i += 256) ss[i] = g_scale[b * HID_ + i];
    __syncthreads();
    for (int i = tid; i < 18432; i += 256) {
        int n  = i / 96;
        int c4 = (i % 96) * 4;
        float4 w = *reinterpret_cast<const float4*>(W2 + (size_t)n * HID_ + c4);
        w.x *= ss[c4 + 0]; w.y *= ss[c4 + 1];
        w.z *= ss[c4 + 2]; w.w *= ss[c4 + 3];
        __half h0, l0, h1, l1, h2, l2, h3, l3;
        split16(w.x, h0, l0); split16(w.y, h1, l1);
        split16(w.z, h2, l2); split16(w.w, h3, l3);
        size_t dst = ((size_t)b * H_ + n) * HID_ + c4;
        *reinterpret_cast<__half2*>(g_w2bh + dst)     = __halves2half2(h0, h1);
        *reinterpret_cast<__half2*>(g_w2bh + dst + 2) = __halves2half2(h2, h3);
        *reinterpret_cast<__half2*>(g_w2bl + dst)     = __halves2half2(l0, l1);
        *reinterpret_cast<__half2*>(g_w2bl + dst + 2) = __halves2half2(l2, l3);
    }
}

// ------------------------- scalar SGEMM for input projection ----------------
__global__ __launch_bounds__(256) void k_gemm3(
    const float* __restrict__ W, const float* __restrict__ bias,
    int K, int N, const float* __restrict__ x_in)
{
    constexpr int BM = 128, BN = 64, BK = 16, TN = 4;
    constexpr int AS = 132, BS = BN + 4;
    __shared__ float As[BK * AS];
    __shared__ float Bs[BK * BS];

    const int m0 = blockIdx.y * BM;
    const int n0 = blockIdx.x * BN;
    const int tid = threadIdx.x;
    const int tx = tid & 15;
    const int ty = tid >> 4;

    ull acc[4][TN];
#pragma unroll
    for (int p = 0; p < 4; p++)
#pragma unroll
        for (int j = 0; j < TN; j++) acc[p][j] = 0ull;

    for (int k0 = 0; k0 < K; k0 += BK) {
#pragma unroll
        for (int it = 0; it < 2; it++) {
            int f = tid + it * 256;
            int row = f >> 2;
            int k4  = f & 3;
            int grow = m0 + row;
            int gk = k0 + k4 * 4;
            int t = grow & (Q_ - 1);
            int g = gk >> 5;
            int d = gk & 31;
            const float* xr = x_in + (size_t)grow * D_ + d;
            float4 x0 = *reinterpret_cast<const float4*>(xr);
            float4 v;
            if (g == 0) {
                v = x0;
            } else {
                float4 x1 = (t >= 1) ? *reinterpret_cast<const float4*>(xr - D_) : x0;
                if (g == 1) {
                    v = make_float4(x0.x - x1.x, x0.y - x1.y, x0.z - x1.z, x0.w - x1.w);
                } else {
                    float4 x2 = (t >= 2) ? *reinterpret_cast<const float4*>(xr - 2 * D_) : x1;
                    v = make_float4(x0.x - 2.0f * x1.x + x2.x,
                                    x0.y - 2.0f * x1.y + x2.y,
                                    x0.z - 2.0f * x1.z + x2.z,
                                    x0.w - 2.0f * x1.w + x2.w);
                }
            }
            As[(k4 * 4 + 0) * AS + row] = v.x;
            As[(k4 * 4 + 1) * AS + row] = v.y;
            As[(k4 * 4 + 2) * AS + row] = v.z;
            As[(k4 * 4 + 3) * AS + row] = v.w;
        }
        {
            int row = tid >> 2;
            int k4  = tid & 3;
            float4 v = *reinterpret_cast<const float4*>(W + (size_t)(n0 + row) * K + (k0 + k4 * 4));
            Bs[(k4 * 4 + 0) * BS + row] = v.x;
            Bs[(k4 * 4 + 1) * BS + row] = v.y;
            Bs[(k4 * 4 + 2) * BS + row] = v.z;
            Bs[(k4 * 4 + 3) * BS + row] = v.w;
        }
        __syncthreads();

#pragma unroll
        for (int kk = 0; kk < BK; kk++) {
            const ulonglong2* a2 = reinterpret_cast<const ulonglong2*>(&As[kk * AS + ty * 8]);
            ulonglong2 q0 = a2[0], q1 = a2[1];
            ull ap[4];
            ap[0] = q0.x; ap[1] = q0.y; ap[2] = q1.x; ap[3] = q1.y;
            float4 tb = *reinterpret_cast<const float4*>(&Bs[kk * BS + tx * TN]);
            ull bd[4];
            bd[0] = dup2(tb.x); bd[1] = dup2(tb.y); bd[2] = dup2(tb.z); bd[3] = dup2(tb.w);
#pragma unroll
            for (int p = 0; p < 4; p++)
#pragma unroll
                for (int j = 0; j < TN; j++)
                    acc[p][j] = ff2(ap[p], bd[j], acc[p][j]);
        }
        __syncthreads();
    }

    float4 bia = *reinterpret_cast<const float4*>(bias + n0 + tx * TN);
#pragma unroll
    for (int p = 0; p < 4; p++) {
#pragma unroll
        for (int hf = 0; hf < 2; hf++) {
            int row = m0 + ty * 8 + p * 2 + hf;
            float4 o;
            o.x = (hf ? hi2(acc[p][0]) : lo2(acc[p][0])) + bia.x;
            o.y = (hf ? hi2(acc[p][1]) : lo2(acc[p][1])) + bia.y;
            o.z = (hf ? hi2(acc[p][2]) : lo2(acc[p][2])) + bia.z;
            o.w = (hf ? hi2(acc[p][3]) : lo2(acc[p][3])) + bia.w;
            *reinterpret_cast<float4*>(g_h + (size_t)row * N + n0 + tx * TN) = o;
        }
    }
}

// ------------------------- depthwise conv + LN -> fp16 split ----------------
__global__ __launch_bounds__(256) void k_conv(
    const float* __restrict__ dw_w, const float* __restrict__ dw_b,
    const float* __restrict__ ln_w, const float* __restrict__ ln_b)
{
    __shared__ float s_in[24][H_];
    __shared__ float s_out[16][H_];
    __shared__ float s_w[H_ * 9];
    __shared__ float s_b[H_];

    const int b  = blockIdx.y;
    const int t0 = blockIdx.x * 16;
    const int tid = threadIdx.x;

    for (int i = tid; i < H_ * 9; i += 256) s_w[i] = dw_w[i];
    for (int i = tid; i < H_; i += 256) s_b[i] = dw_b[i];
    for (int i = tid; i < 24 * H_; i += 256) {
        int r = i / H_, ch = i % H_;
        int t = t0 + r - 4;
        t = min(max(t, 0), Q_ - 1);
        s_in[r][ch] = g_h[((size_t)b * Q_ + t) * H_ + ch];
    }
    __syncthreads();

    for (int i = tid; i < 16 * H_; i += 256) {
        int r = i / H_, ch = i % H_;
        float acc = s_b[ch];
#pragma unroll
        for (int k = 0; k < 9; k++) acc = fmaf(s_in[r + k][ch], s_w[ch * 9 + k], acc);
        s_out[r][ch] = acc;
    }
    __syncthreads();

    const int wid = tid >> 5, lane = tid & 31;
#pragma unroll
    for (int rr = 0; rr < 2; rr++) {
        int r = wid * 2 + rr;
        float v[6], sum = 0.0f;
#pragma unroll
        for (int j = 0; j < 6; j++) { v[j] = s_out[r][j * 32 + lane]; sum += v[j]; }
        sum = warp_sum(sum);
        float mean = sum * (1.0f / H_);
        float var = 0.0f;
#pragma unroll
        for (int j = 0; j < 6; j++) { float d = v[j] - mean; var = fmaf(d, d, var); }
        var = warp_sum(var) * (1.0f / H_);
        float inv = rsqrtf(var + 1e-5f);
        size_t base = ((size_t)b * Q_ + t0 + r) * H_;
#pragma unroll
        for (int j = 0; j < 6; j++) {
            int ch = j * 32 + lane;
            float val = (v[j] - mean) * inv * ln_w[ch] + ln_b[ch];
            __half hi, lo;
            split16(val, hi, lo);
            g_yh[base + ch] = hi;
            g_yl[base + ch] = lo;
        }
    }
}

// ------------------------- out-LN + rho/phi/gain -----------------------------
__global__ __launch_bounds__(256) void k_rpg(
    const float* __restrict__ out_ln_w, const float* __restrict__ out_ln_b,
    const float* __restrict__ fc_rp_w, const float* __restrict__ fc_rp_b,
    const float* __restrict__ fc_gain_w, const float* __restrict__ fc_gain_b)
{
    const int wid = threadIdx.x >> 5, lane = threadIdx.x & 31;
    const int row = blockIdx.x * 8 + wid;
    const float* hp = g_h + (size_t)row * H_;

    float v[6], sum = 0.0f;
#pragma unroll
    for (int j = 0; j < 6; j++) { v[j] = hp[j * 32 + lane]; sum += v[j]; }
    sum = warp_sum(sum);
    float mean = sum * (1.0f / H_);
    float var = 0.0f;
#pragma unroll
    for (int j = 0; j < 6; j++) { float d = v[j] - mean; var = fmaf(d, d, var); }
    var = warp_sum(var) * (1.0f / H_);
    float inv = rsqrtf(var + 1e-5f);

    float hn[6];
#pragma unroll
    for (int j = 0; j < 6; j++) {
        int ch = j * 32 + lane;
        hn[j] = (v[j] - mean) * inv * out_ln_w[ch] + out_ln_b[ch];
    }

    int t = row & (Q_ - 1), b = row >> 9;
    if (t == Q_ - 1) {
#pragma unroll
        for (int j = 0; j < 6; j++) g_hr[b * H_ + j * 32 + lane] = hn[j];
    }

#pragma unroll
    for (int o = 0; o < 2; o++) {
        float a = 0.0f;
#pragma unroll
        for (int j = 0; j < 6; j++) a = fmaf(hn[j], fc_rp_w[o * H_ + j * 32 + lane], a);
        a = warp_sum(a);
        if (lane == 0) {
            float z = a + fc_rp_b[o];
            g_rp[row * 2 + o] = (o == 0) ? 1.25f * sigf(z) : PI_ * tanhf(z);
        }
    }
    for (int d = 0; d < D_; d++) {
        float a = 0.0f;
#pragma unroll
        for (int j = 0; j < 6; j++) a = fmaf(hn[j], fc_gain_w[d * H_ + j * 32 + lane], a);
        a = warp_sum(a);
        if (lane == 0) g_gain[(size_t)row * D_ + d] = sigf(a + fc_gain_b[d]);
    }
}

// ------------------------- Kalman scan ---------------------------------------
__global__ void k_scan(const float* __restrict__ x_in) {
    const int wid = threadIdx.x >> 5, lane = threadIdx.x & 31;
    const int b = blockIdx.x * 4 + wid;
    const int base = b * Q_;

    float x  = x_in[(size_t)base * D_ + lane];
    float2 rp = *reinterpret_cast<const float2*>(g_rp + base * 2);
    float gn = g_gain[(size_t)base * D_ + lane];
    float y  = x;

    for (int t = 0; t < Q_; t++) {
        float2 rp_n = rp; float gn_n = gn, y_n = y;
        if (t + 1 < Q_) {
            rp_n = *reinterpret_cast<const float2*>(g_rp + (base + t + 1) * 2);
            gn_n = g_gain[(size_t)(base + t + 1) * D_ + lane];
            y_n  = x_in[(size_t)(base + t + 1) * D_ + lane];
        }
        float s, c;
        sincosf(rp.y, &s, &c);
        float partner = __shfl_xor_sync(0xffffffffu, x, 16);
        float xp = (lane < 16) ? rp.x * (c * x - s * partner)
                               : rp.x * (s * partner + c * x);
        x = xp + gn * (y - xp);
        rp = rp_n; gn = gn_n; y = y_n;
    }
    g_curr[b * D_ + lane] = x;
}

// ------------------------- packing ------------------------------------------
__global__ void k_pack(const float* __restrict__ roll_in_w, const float* __restrict__ roll_in_b,
                       const float* __restrict__ gru_whh, const float* __restrict__ gru_bhh,
                       const float* __restrict__ gru_wih,
                       const float* __restrict__ b_pw1_w, const float* __restrict__ b_pw2_w,
                       const float* __restrict__ b_pw2_b, const float* __restrict__ b_grn_b)
{
    int i = blockIdx.x * 256 + threadIdx.x;
    constexpr int NA = 56 * 768 * 4;                 // 172032
    constexpr int NB = NA + 768;                     // 172800
    constexpr int NW = NB + 48 * 576 * 4;            // 283392
    constexpr int NW1 = NW + 2 * HID_ * H_;          // 430848
    constexpr int NB2 = NW1 + 2 * H_ * 32;           // warp-per-output
    if (i < NA) {
        int k4 = i / (768 * 4);
        int rem = i % (768 * 4);
        int c = rem >> 2;
        int j = rem & 3;
        int k = 4 * k4 + j;
        float v;
        if (c < 192)      v = roll_in_w[c * 224 + k];
        else if (k < 192) v = gru_whh[(c - 192) * 192 + k];
        else              v = 0.0f;
        g_pA4[i] = v;
    } else if (i < NB) {
        int c = i - NA;
        g_bA[c] = (c < 192) ? roll_in_b[c] : gru_bhh[c - 192];
    } else if (i < NW) {
        int t = i - NB;
        int k4 = t / (576 * 4);
        int rem = t % (576 * 4);
        int o = rem >> 2;
        int j = rem & 3;
        g_wih4[t] = gru_wih[o * 192 + 4 * k4 + j];
    } else if (i < NW1) {
        int j = i - NW;
        __half hi, lo;
        split16(b_pw1_w[j], hi, lo);
        g_w1h[j] = hi;
        g_w1l[j] = lo;
    } else if (i < NB2) {
        int j = i - NW1;
        int out = j >> 5, lane = j & 31;     // out < 384
        int blk = out / H_, n = out % H_;
        const float* w = b_pw2_w + (size_t)blk * H_ * HID_ + (size_t)n * HID_;
        const float* gb = b_grn_b + blk * HID_;
        float s = 0.0f;
        for (int k = lane; k < HID_; k += 32) s = fmaf(gb[k], w[k], s);
        s = warp_sum(s);
        if (lane == 0) g_bias2[out] = s + b_pw2_b[out];
    }
}

// ------------------------- persistent GRU rollout ----------------------------
__global__ __launch_bounds__(256) void k_roll(
    const float* __restrict__ gru_bih,
    const float* __restrict__ roll_ln_w, const float* __restrict__ roll_ln_b,
    const float* __restrict__ fc_rp_r_w, const float* __restrict__ fc_rp_r_b,
    float* __restrict__ out, int w_out)
{
    __shared__ float sSt[224][4];
    __shared__ float sx [192][4];
    __shared__ float sgh[4][576];
    __shared__ float sgi[4][576];
    __shared__ float spre[4][192];

    const int r0 = blockIdx.x * 4;
    const int tid = threadIdx.x;
    const int wid = tid >> 5, lane = tid & 31;

    const float4* pA4  = reinterpret_cast<const float4*>(g_pA4);
    const float4* wih4 = reinterpret_cast<const float4*>(g_wih4);

    for (int i = tid; i < 4 * 224; i += 256) {
        int r = i / 224, k = i % 224;
        sSt[k][r] = (k < 192) ? g_hr[(r0 + r) * H_ + k]
                              : g_curr[(r0 + r) * D_ + (k - 192)];
    }
    __syncthreads();

    for (int step = 0; step < w_out; step++) {
        {
            ull a01[3], a23[3];
#pragma unroll
            for (int j = 0; j < 3; j++) { a01[j] = 0ull; a23[j] = 0ull; }
#pragma unroll 4
            for (int k4 = 0; k4 < 56; k4++) {
                float4 w0 = __ldg(pA4 + k4 * 768 + tid);
                float4 w1 = __ldg(pA4 + k4 * 768 + tid + 256);
                float4 w2 = __ldg(pA4 + k4 * 768 + tid + 512);
                ull p01[4], p23[4];
#pragma unroll
                for (int j = 0; j < 4; j++) {
                    p01[j] = *reinterpret_cast<const ull*>(&sSt[k4 * 4 + j][0]);
                    p23[j] = *reinterpret_cast<const ull*>(&sSt[k4 * 4 + j][2]);
                }
                ull b;
                b = dup2(w0.x); a01[0]=ff2(p01[0],b,a01[0]); a23[0]=ff2(p23[0],b,a23[0]);
                b = dup2(w0.y); a01[0]=ff2(p01[1],b,a01[0]); a23[0]=ff2(p23[1],b,a23[0]);
                b = dup2(w0.z); a01[0]=ff2(p01[2],b,a01[0]); a23[0]=ff2(p23[2],b,a23[0]);
                b = dup2(w0.w); a01[0]=ff2(p01[3],b,a01[0]); a23[0]=ff2(p23[3],b,a23[0]);
                b = dup2(w1.x); a01[1]=ff2(p01[0],b,a01[1]); a23[1]=ff2(p23[0],b,a23[1]);
                b = dup2(w1.y); a01[1]=ff2(p01[1],b,a01[1]); a23[1]=ff2(p23[1],b,a23[1]);
                b = dup2(w1.z); a01[1]=ff2(p01[2],b,a01[1]); a23[1]=ff2(p23[2],b,a23[1]);
                b = dup2(w1.w); a01[1]=ff2(p01[3],b,a01[1]); a23[1]=ff2(p23[3],b,a23[1]);
                b = dup2(w2.x); a01[2]=ff2(p01[0],b,a01[2]); a23[2]=ff2(p23[0],b,a23[2]);
                b = dup2(w2.y); a01[2]=ff2(p01[1],b,a01[2]); a23[2]=ff2(p23[1],b,a23[2]);
                b = dup2(w2.z); a01[2]=ff2(p01[2],b,a01[2]); a23[2]=ff2(p23[2],b,a23[2]);
                b = dup2(w2.w); a01[2]=ff2(p01[3],b,a01[2]); a23[2]=ff2(p23[3],b,a23[2]);
            }
#pragma unroll
            for (int j = 0; j < 3; j++) {
                int c = tid + j * 256;
                float bia = g_bA[c];
                float v0 = lo2(a01[j]) + bia;
                float v1 = hi2(a01[j]) + bia;
                float v2 = lo2(a23[j]) + bia;
                float v3 = hi2(a23[j]) + bia;
                if (c < 192) {
                    sx[c][0] = tanhf(v0); sx[c][1] = tanhf(v1);
                    sx[c][2] = tanhf(v2); sx[c][3] = tanhf(v3);
                } else {
                    int o = c - 192;
                    sgh[0][o] = v0; sgh[1][o] = v1; sgh[2][o] = v2; sgh[3][o] = v3;
                }
            }
        }
        __syncthreads();

        {
            ull a01[3], a23[3];
#pragma unroll
            for (int j = 0; j < 3; j++) { a01[j] = 0ull; a23[j] = 0ull; }
            int o2c = (tid < 64) ? (tid + 512) : 575;
#pragma unroll 4
            for (int k4 = 0; k4 < 48; k4++) {
                float4 w0 = __ldg(wih4 + k4 * 576 + tid);
                float4 w1 = __ldg(wih4 + k4 * 576 + tid + 256);
                float4 w2 = __ldg(wih4 + k4 * 576 + o2c);
                ull p01[4], p23[4];
#pragma unroll
                for (int j = 0; j < 4; j++) {
                    p01[j] = *reinterpret_cast<const ull*>(&sx[k4 * 4 + j][0]);
                    p23[j] = *reinterpret_cast<const ull*>(&sx[k4 * 4 + j][2]);
                }
                ull b;
                b = dup2(w0.x); a01[0]=ff2(p01[0],b,a01[0]); a23[0]=ff2(p23[0],b,a23[0]);
                b = dup2(w0.y); a01[0]=ff2(p01[1],b,a01[0]); a23[0]=ff2(p23[1],b,a23[0]);
                b = dup2(w0.z); a01[0]=ff2(p01[2],b,a01[0]); a23[0]=ff2(p23[2],b,a23[0]);
                b = dup2(w0.w); a01[0]=ff2(p01[3],b,a01[0]); a23[0]=ff2(p23[3],b,a23[0]);
                b = dup2(w1.x); a01[1]=ff2(p01[0],b,a01[1]); a23[1]=ff2(p23[0],b,a23[1]);
                b = dup2(w1.y); a01[1]=ff2(p01[1],b,a01[1]); a23[1]=ff2(p23[1],b,a23[1]);
                b = dup2(w1.z); a01[1]=ff2(p01[2],b,a01[1]); a23[1]=ff2(p23[2],b,a23[1]);
                b = dup2(w1.w); a01[1]=ff2(p01[3],b,a01[1]); a23[1]=ff2(p23[3],b,a23[1]);
                b = dup2(w2.x); a01[2]=ff2(p01[0],b,a01[2]); a23[2]=ff2(p23[0],b,a23[2]);
                b = dup2(w2.y); a01[2]=ff2(p01[1],b,a01[2]); a23[2]=ff2(p23[1],b,a23[2]);
                b = dup2(w2.z); a01[2]=ff2(p01[2],b,a01[2]); a23[2]=ff2(p23[2],b,a23[2]);
                b = dup2(w2.w); a01[2]=ff2(p01[3],b,a01[2]); a23[2]=ff2(p23[3],b,a23[2]);
            }
#pragma unroll
            for (int j = 0; j < 3; j++) {
                int o = tid + j * 256;
                if (o < 576) {
                    float bia = gru_bih[o];
                    sgi[0][o] = lo2(a01[j]) + bia;
                    sgi[1][o] = hi2(a01[j]) + bia;
                    sgi[2][o] = lo2(a23[j]) + bia;
                    sgi[3][o] = hi2(a23[j]) + bia;
                }
            }
        }
        __syncthreads();

#pragma unroll
        for (int ii = 0; ii < 3; ii++) {
            int idx = tid + ii * 256;
            int r = idx / 192, ch = idx - r * 192;
            float rg = sigf(sgi[r][ch] + sgh[r][ch]);
            float zg = sigf(sgi[r][192 + ch] + sgh[r][192 + ch]);
            float ng = tanhf(sgi[r][384 + ch] + rg * sgh[r][384 + ch]);
            float hr = sSt[ch][r];
            spre[r][ch] = (1.0f - zg) * ng + zg * hr;
        }
        __syncthreads();

        if (wid < 4) {
            int r = wid, row = r0 + r;
            float v[6], sum = 0.0f;
#pragma unroll
            for (int j = 0; j < 6; j++) { v[j] = spre[r][j * 32 + lane]; sum += v[j]; }
            sum = warp_sum(sum);
            float mean = sum * (1.0f / H_);
            float var = 0.0f;
#pragma unroll
            for (int j = 0; j < 6; j++) { float d = v[j] - mean; var = fmaf(d, d, var); }
            var = warp_sum(var) * (1.0f / H_);
            float inv = rsqrtf(var + 1e-5f);

            float p0 = 0.0f, p1 = 0.0f;
#pragma unroll
            for (int j = 0; j < 6; j++) {
                int ch = j * 32 + lane;
                float hn = (v[j] - mean) * inv * roll_ln_w[ch] + roll_ln_b[ch];
                sSt[ch][r] = hn;
                p0 = fmaf(hn, fc_rp_r_w[ch], p0);
                p1 = fmaf(hn, fc_rp_r_w[H_ + ch], p1);
            }
            p0 = warp_sum(p0);
            p1 = warp_sum(p1);
            float rho = 1.25f * sigf(p0 + fc_rp_r_b[0]);
            float phi = PI_ * tanhf(p1 + fc_rp_r_b[1]);
            float s, c;
            sincosf(phi, &s, &c);
            float cur = sSt[192 + lane][r];
            float partner = __shfl_xor_sync(0xffffffffu, cur, 16);
            float nv = (lane < 16) ? rho * (c * cur - s * partner)
                                   : rho * (s * partner + c * cur);
            sSt[192 + lane][r] = nv;
            out[((size_t)row * w_out + step) * D_ + lane] = nv;
        }
        __syncthreads();
    }
}

// -----------------------------------------------------------------------------
extern "C" void kernel_launch(void* const* d_in, const int* in_sizes, int n_in,
                              void* d_out, int out_size) {
    const float* x_in      = (const float*)d_in[0];
    const float* inp_w     = (const float*)d_in[1];
    const float* inp_b     = (const float*)d_in[2];
    const float* b_dw_w    = (const float*)d_in[3];
    const float* b_dw_b    = (const float*)d_in[4];
    const float* b_ln_w    = (const float*)d_in[5];
    const float* b_ln_b    = (const float*)d_in[6];
    const float* b_pw1_w   = (const float*)d_in[7];
    const float* b_pw1_b   = (const float*)d_in[8];
    const float* b_grn_g   = (const float*)d_in[9];
    const float* b_grn_b   = (const float*)d_in[10];
    const float* b_pw2_w   = (const float*)d_in[11];
    const float* b_pw2_b   = (const float*)d_in[12];
    const float* out_ln_w  = (const float*)d_in[13];
    const float* out_ln_b  = (const float*)d_in[14];
    const float* fc_rp_w   = (const float*)d_in[15];
    const float* fc_rp_b   = (const float*)d_in[16];
    const float* fc_gain_w = (const float*)d_in[17];
    const float* fc_gain_b = (const float*)d_in[18];
    const float* roll_in_w = (const float*)d_in[19];
    const float* roll_in_b = (const float*)d_in[20];
    const float* gru_wih   = (const float*)d_in[21];
    const float* gru_whh   = (const float*)d_in[22];
    const float* gru_bih   = (const float*)d_in[23];
    const float* gru_bhh   = (const float*)d_in[24];
    const float* roll_ln_w = (const float*)d_in[25];
    const float* roll_ln_b = (const float*)d_in[26];
    const float* fc_rp_r_w = (const float*)d_in[27];
    const float* fc_rp_r_b = (const float*)d_in[28];

    float* out = (float*)d_out;
    const int w_out = out_size / (B_ * D_);

    constexpr int SMX = 65536 + 1024;   // 2-stage A(hi/lo)+W(hi/lo) + aux
    cudaFuncSetAttribute(k_mma<1>, cudaFuncAttributeMaxDynamicSharedMemorySize, SMX);
    cudaFuncSetAttribute(k_mma<2>, cudaFuncAttributeMaxDynamicSharedMemorySize, SMX);

    // 0. pack rollout weights + pw1 split + parallel pw2 effective bias
    k_pack<<<(443136 + 255) / 256, 256>>>(
        roll_in_w, roll_in_b, gru_whh, gru_bhh, gru_wih,
        b_pw1_w, b_pw2_w, b_pw2_b, b_grn_b);

    // 1. input projection with features on the fly: x_in -> g_h
    {
        dim3 grid(H_ / 64, BQ_ / 128);
        k_gemm3<<<grid, 256>>>(inp_w, inp_b, INC_, H_, x_in);
    }

    // 2. ConvNeXt blocks
    for (int blk = 0; blk < 2; blk++) {
        {
            dim3 grid(Q_ / 16, B_);
            k_conv<<<grid, 256>>>(b_dw_w + blk * H_ * 9, b_dw_b + blk * H_,
                                  b_ln_w + blk * H_,     b_ln_b + blk * H_);
        }
        {
            // pw1 + GELU + GRN partials -> split y1   [profile index 3]
            dim3 grid(HID_ / 64, BQ_ / 64);
            k_mma<1><<<grid, 256, SMX>>>(blk, b_pw1_b + blk * HID_, H_, HID_);
        }
        // GRN scale per batch, then per-batch scaled-split W2
        k_grn2<<<B_, HID_>>>(b_grn_g + blk * HID_);
        k_wsplit<<<B_, 256>>>(b_pw2_w + (size_t)blk * H_ * HID_);
        {
            // pw2: pre-scaled W, bias2, residual -> g_h
            dim3 grid(H_ / 64, BQ_ / 64);
            k_mma<2><<<grid, 256, SMX>>>(blk, nullptr, HID_, H_);
        }
    }

    // 3. out-LN + rho/phi/gain
    k_rpg<<<BQ_ / 8, 256>>>(out_ln_w, out_ln_b, fc_rp_w, fc_rp_b,
                            fc_gain_w, fc_gain_b);

    // 4. Kalman scan
    k_scan<<<B_ / 4, 128>>>(x_in);

    // 5. persistent GRU rollout
    k_roll<<<B_ / 4, 256>>>(gru_bih, roll_ln_w, roll_ln_b,
                            fc_rp_r_w, fc_rp_r_b, out, w_out);
}